// round 13
// baseline (speedup 1.0000x reference)
#include <cuda_runtime.h>
#include <cuda_bf16.h>
#include <cstdint>
#include <math.h>

#define EMBD 512
#define NHEADS 8
#define HDIM 64
#define NDEPTH 6
#define NCONT 100
#define NCAT 28
#define NHID 682
#define BSZ 128
#define SEQ 129
#define NTOK (BSZ*SEQ)      /* 16512 */
#define QKVN (3*EMBD)       /* 1536  */
#define HID2 (2*NHID)       /* 1364  */
#define NBH (BSZ*NHEADS)    /* 1024  */

#define KPAD_E 512
#define KPAD_H 704
#define W0_NPAD 1536
#define QSCALE 22.62741699796952f

// ---------------- scratch (device globals) ---------------------------------
__device__ float g_h[NTOK*EMBD];
__device__ float g_qkv[NTOK*QKVN];                           // only v part used now
__device__ __nv_bfloat16 g_qk[(size_t)NBH*2*SEQ*128];        // q,k split-bf16 rows
__device__ __nv_bfloat16 g_a2[(size_t)NTOK*1024];            // EMB-K operand
__device__ __nv_bfloat16 g_r[(size_t)NTOK*1408];             // reglu operand (Kpad=704)
#define B2_QKV_SZ ((size_t)1536*1024)
#define B2_WOUT_SZ ((size_t)512*1024)
#define B2_W0_SZ ((size_t)W0_NPAD*1024)
#define B2_W1_SZ ((size_t)512*1408)
#define B2_LAYER (B2_QKV_SZ+B2_WOUT_SZ+B2_W0_SZ+B2_W1_SZ)
__device__ __nv_bfloat16 g_b2[B2_LAYER*NDEPTH];

// ---------------- helpers ---------------------------------------------------
__device__ __forceinline__ uint32_t smem_u32(const void* p) {
    uint32_t a;
    asm("{ .reg .u64 t; cvta.to.shared.u64 t, %1; cvt.u32.u64 %0, t; }" : "=r"(a) : "l"(p));
    return a;
}
#define LDSM4(r0, r1, r2, r3, addr) \
    asm volatile("ldmatrix.sync.aligned.m8n8.x4.shared.b16 {%0,%1,%2,%3}, [%4];" \
        : "=r"(r0), "=r"(r1), "=r"(r2), "=r"(r3) : "r"(addr))
#define LDSM2(r0, r1, addr) \
    asm volatile("ldmatrix.sync.aligned.m8n8.x2.shared.b16 {%0,%1}, [%2];" \
        : "=r"(r0), "=r"(r1) : "r"(addr))
#define MMA16816(d, a, b) \
    asm volatile("mma.sync.aligned.m16n8k16.row.col.f32.bf16.bf16.f32 " \
        "{%0,%1,%2,%3},{%4,%5,%6,%7},{%8,%9},{%0,%1,%2,%3};" \
        : "+f"((d)[0]), "+f"((d)[1]), "+f"((d)[2]), "+f"((d)[3]) \
        : "r"((a)[0]), "r"((a)[1]), "r"((a)[2]), "r"((a)[3]), "r"((b)[0]), "r"((b)[1]))
#define CPA16(s, g) \
    asm volatile("cp.async.cg.shared.global [%0], [%1], 16;" :: "r"(s), "l"(g))
#define CPA_COMMIT asm volatile("cp.async.commit_group;" ::: "memory")
#define CPA_WAIT(n) asm volatile("cp.async.wait_group %0;" :: "n"(n) : "memory")

__device__ __forceinline__ void split_bf16(float v, __nv_bfloat16& hi, __nv_bfloat16& lo) {
    hi = __float2bfloat16(v);
    lo = __float2bfloat16(v - __bfloat162float(hi));
}

// ---------------- HMMA GEMM: 3-pass bf16 split -----------------------------
// mode 0: C=acc+bias ; 1: +=res ; 2: reglu->Rout ; 3: qkv (q,k split->Rout, v fp32->C)
#define PITCH 144
#define ABUF (128*PITCH)
#define BBUF (128*PITCH)
#define BOFF (3*ABUF)
#define GEMM_SMEM (3*(ABUF+BBUF))     /* 110592 B */
__global__ void __launch_bounds__(256, 2)
gemm_mma(const __nv_bfloat16* __restrict__ A2, const __nv_bfloat16* __restrict__ B2,
         const float* __restrict__ bias, const float* __restrict__ res,
         float* __restrict__ C, __nv_bfloat16* __restrict__ Rout,
         int Nact, int Cs, int Kpad, int mode) {
    extern __shared__ __nv_bfloat16 dsm[];
    const uint32_t sbase = smem_u32(dsm);
    const int tid = threadIdx.x, lane = tid & 31, wid = tid >> 5;
    const int wm = wid & 1, wn = wid >> 1;
    const int m0 = blockIdx.x * 128, n0 = blockIdx.y * 128;
    const int sA2 = 2 * Kpad;
    const int KC = Kpad >> 6;
    const int nsteps = 3 * KC;

    float acc[4][4][4];
#pragma unroll
    for (int a = 0; a < 4; a++)
#pragma unroll
        for (int b = 0; b < 4; b++)
#pragma unroll
            for (int c = 0; c < 4; c++) acc[a][b][c] = 0.f;

    const int rT = tid >> 3, cT = tid & 7;
    const uint32_t sA0 = sbase + rT * PITCH + cT * 16;
    const uint32_t sB0 = sbase + BOFF + rT * PITCH + cT * 16;
    const __nv_bfloat16* gA0 = A2 + (size_t)(m0 + rT) * sA2 + cT * 8;
    const __nv_bfloat16* gB0 = B2 + (size_t)(n0 + rT) * sA2 + cT * 8;

#define ISSUE(i) do { \
    int pass = ((i) >= 2 * KC) ? 2 : (((i) >= KC) ? 1 : 0); \
    int kc = (i) - pass * KC; \
    int aO = ((pass == 2) ? Kpad : 0) + kc * 64; \
    int bO = ((pass == 1) ? Kpad : 0) + kc * 64; \
    int bufi = (i) % 3; \
    uint32_t sa = sA0 + bufi * ABUF; \
    uint32_t sb = sB0 + bufi * BBUF; \
    CPA16(sa,             gA0 + aO); \
    CPA16(sa + 32*PITCH,  gA0 + aO + (size_t)32 * sA2); \
    CPA16(sa + 64*PITCH,  gA0 + aO + (size_t)64 * sA2); \
    CPA16(sa + 96*PITCH,  gA0 + aO + (size_t)96 * sA2); \
    CPA16(sb,             gB0 + bO); \
    CPA16(sb + 32*PITCH,  gB0 + bO + (size_t)32 * sA2); \
    CPA16(sb + 64*PITCH,  gB0 + bO + (size_t)64 * sA2); \
    CPA16(sb + 96*PITCH,  gB0 + bO + (size_t)96 * sA2); \
    CPA_COMMIT; \
} while (0)

    const int q = lane >> 3, rr = lane & 7;
    const uint32_t aBase = sbase +
        (uint32_t)((wm * 64 + (q & 1) * 8 + rr) * PITCH + (q >> 1) * 16);
    const uint32_t bBase = sbase + BOFF +
        (uint32_t)((wn * 32 + (q >> 1) * 8 + rr) * PITCH + (q & 1) * 16);

    ISSUE(0);
    ISSUE(1);

    for (int i = 0; i < nsteps; i++) {
        if (i == nsteps - 1) CPA_WAIT(0); else CPA_WAIT(1);
        __syncthreads();
        if (i + 2 < nsteps) ISSUE(i + 2);
        const int buf = i % 3;
        const uint32_t aB = aBase + buf * ABUF;
        const uint32_t bB = bBase + buf * BBUF;
#pragma unroll
        for (int kk = 0; kk < 4; kk++) {
            uint32_t af[4][4];
#pragma unroll
            for (int mi = 0; mi < 4; mi++)
                LDSM4(af[mi][0], af[mi][1], af[mi][2], af[mi][3],
                      aB + mi * (16 * PITCH) + kk * 32);
            uint32_t bfr[4][2];
#pragma unroll
            for (int g = 0; g < 2; g++) {
                uint32_t t0, t1, t2, t3;
                LDSM4(t0, t1, t2, t3, bB + g * (16 * PITCH) + kk * 32);
                bfr[2 * g][0] = t0;     bfr[2 * g][1] = t1;
                bfr[2 * g + 1][0] = t2; bfr[2 * g + 1][1] = t3;
            }
#pragma unroll
            for (int mi = 0; mi < 4; mi++)
#pragma unroll
                for (int ni = 0; ni < 4; ni++)
                    MMA16816(acc[mi][ni], af[mi], bfr[ni]);
        }
    }

    // epilogue
    if (mode == 2) {
#pragma unroll
        for (int mi = 0; mi < 4; mi++) {
            int r0 = m0 + wm * 64 + mi * 16 + (lane >> 2);
            __nv_bfloat16* d0 = Rout + (size_t)r0 * 1408;
            __nv_bfloat16* d1 = Rout + (size_t)(r0 + 8) * 1408;
#pragma unroll
            for (int ni = 0; ni < 4; ni++) {
                int c0 = n0 + wn * 32 + ni * 8 + (lane & 3) * 2;
                if (c0 < HID2) {
                    int j = c0 >> 1;
                    float ba = bias[j], bb = bias[NHID + j];
                    float v0 = (acc[mi][ni][0] + ba) * fmaxf(acc[mi][ni][1] + bb, 0.f);
                    float v1 = (acc[mi][ni][2] + ba) * fmaxf(acc[mi][ni][3] + bb, 0.f);
                    __nv_bfloat16 hi, lo;
                    split_bf16(v0, hi, lo); d0[j] = hi; d0[704 + j] = lo;
                    split_bf16(v1, hi, lo); d1[j] = hi; d1[704 + j] = lo;
                }
            }
        }
    } else if (mode == 3) {
        // qkv: cols -> head/part/d. q,k: split-bf16 rows [hi64|lo64]; v: fp32
#pragma unroll
        for (int mi = 0; mi < 4; mi++) {
            int r0g = m0 + wm * 64 + mi * 16 + (lane >> 2);
#pragma unroll
            for (int half = 0; half < 2; half++) {
                int m = r0g + half * 8;
                int bb = m / SEQ;
                int tok = m - bb * SEQ;
#pragma unroll
                for (int ni = 0; ni < 4; ni++) {
                    int c0 = n0 + wn * 32 + ni * 8 + (lane & 3) * 2;
                    int head = c0 / 192;
                    int rem = c0 - head * 192;
                    int part = rem >> 6;
                    int d = rem & 63;
                    float2 bv = *(const float2*)&bias[c0];
                    float v0 = acc[mi][ni][half * 2]     + bv.x;
                    float v1 = acc[mi][ni][half * 2 + 1] + bv.y;
                    if (part == 2) {
                        float* cr = C + (size_t)m * Cs + c0;
                        cr[0] = v0; cr[1] = v1;
                    } else {
                        if (part == 0) { v0 *= QSCALE; v1 *= QSCALE; }
                        __nv_bfloat16* dst = Rout +
                            ((size_t)((bb * 8 + head) * 2 + part) * SEQ + tok) * 128 + d;
                        __nv_bfloat16 h0, l0, h1, l1;
                        split_bf16(v0, h0, l0);
                        split_bf16(v1, h1, l1);
                        __nv_bfloat162 ph; ph.x = h0; ph.y = h1;
                        __nv_bfloat162 pl; pl.x = l0; pl.y = l1;
                        *(__nv_bfloat162*)dst = ph;
                        *(__nv_bfloat162*)(dst + 64) = pl;
                    }
                }
            }
        }
    } else {
#pragma unroll
        for (int mi = 0; mi < 4; mi++) {
            int r0 = m0 + wm * 64 + mi * 16 + (lane >> 2);
            float* cr0 = C + (size_t)r0 * Cs;
            float* cr1 = C + (size_t)(r0 + 8) * Cs;
            const float* rr0 = res + (size_t)r0 * Cs;
            const float* rr1 = res + (size_t)(r0 + 8) * Cs;
#pragma unroll
            for (int ni = 0; ni < 4; ni++) {
                int c0 = n0 + wn * 32 + ni * 8 + (lane & 3) * 2;
                if (c0 < Nact) {
                    float2 bv = *(const float2*)&bias[c0];
                    float2 v01 = make_float2(acc[mi][ni][0] + bv.x, acc[mi][ni][1] + bv.y);
                    float2 v23 = make_float2(acc[mi][ni][2] + bv.x, acc[mi][ni][3] + bv.y);
                    if (mode == 1) {
                        float2 ra = *(const float2*)&rr0[c0];
                        float2 rb = *(const float2*)&rr1[c0];
                        v01.x += ra.x; v01.y += ra.y;
                        v23.x += rb.x; v23.y += rb.y;
                    }
                    *(float2*)&cr0[c0] = v01;
                    *(float2*)&cr1[c0] = v23;
                }
            }
        }
    }
}

// ---------------- tensor-core fused attention ------------------------------
// Padded tokens T=144. smem layout (bytes):
//   QP  @ 0      : 16 rows x 272   (q hi|lo)          4352
//   KP  @ 4352   : 144 rows x 272  (k hi|lo)         39168
//   VT  @ 43520  : 64 rows x 592   (v^T hi|lo)       37888
//   SB  @ 81408  : 16 rows x 592   (S hi|lo)          9472
//   SF  @ 90880  : 16 rows x 160 fp32                10240
#define AQ_OFF 0
#define AK_OFF 4352
#define AV_OFF 43520
#define ASB_OFF 81408
#define ASF_OFF 90880
#define ATT_SMEM 101120
__global__ void __launch_bounds__(256, 2)
attn_mma(const __nv_bfloat16* __restrict__ qk, const float* __restrict__ qkv,
         __nv_bfloat16* __restrict__ a2) {
    extern __shared__ char smc[];
    const uint32_t sb = smem_u32(smc);
    float* SF = (float*)(smc + ASF_OFF);
    const int bh = blockIdx.x;
    const int b = bh >> 3, h = bh & 7;
    const __nv_bfloat16* gq = qk + (size_t)(bh * 2) * SEQ * 128;
    const __nv_bfloat16* gk = gq + (size_t)SEQ * 128;
    const float* vbase = qkv + (size_t)b * SEQ * QKVN + h * (3 * HDIM) + 2 * HDIM;
    const int t = threadIdx.x, lane = t & 31, w = t >> 5;

    // k: 16B copies into KP (zero pads); v: split into VT
    {
        const uint4 z4 = make_uint4(0, 0, 0, 0);
        for (int idx = t; idx < 144 * 16; idx += 256) {
            int tok = idx >> 4, c = idx & 15;
            uint4 val = (tok < SEQ) ? ((const uint4*)(gk + (size_t)tok * 128))[c] : z4;
            *(uint4*)(smc + AK_OFF + tok * 272 + c * 16) = val;
        }
        for (int idx = t; idx < 144 * 64; idx += 256) {
            int tok = idx >> 6, d = idx & 63;
            float vv = (tok < SEQ) ? vbase[(size_t)tok * QKVN + d] : 0.f;
            __nv_bfloat16 hi, lo;
            split_bf16(vv, hi, lo);
            *(__nv_bfloat16*)(smc + AV_OFF + d * 592 + tok * 2) = hi;
            *(__nv_bfloat16*)(smc + AV_OFF + d * 592 + 288 + tok * 2) = lo;
        }
    }

    const int q4 = lane >> 3, rr = lane & 7;
    const uint32_t aQ = sb + AQ_OFF +
        (uint32_t)(((q4 & 1) * 8 + rr) * 272 + (q4 >> 1) * 16);
    const uint32_t aS = sb + ASB_OFF +
        (uint32_t)(((q4 & 1) * 8 + rr) * 592 + (q4 >> 1) * 16);

    for (int blk = 0; blk < 9; blk++) {
        const int r0m = blk * 16;
        __syncthreads();   // previous block fully consumed QP/SF/SB
        // ---- load q block (pre-scaled split rows; 16B copies) ----
        {
            int r = t >> 4, c = t & 15;
            int m = r0m + r;
            uint4 val = make_uint4(0, 0, 0, 0);
            if (m < SEQ) val = ((const uint4*)(gq + (size_t)m * 128))[c];
            *(uint4*)(smc + AQ_OFF + r * 272 + c * 16) = val;
        }
        __syncthreads();
        // ---- S = q @ k^T (mma, 3-pass) ----
        for (int g = w; g < 9; g += 8) {
            float c0[4] = {0.f, 0.f, 0.f, 0.f};
            float c1[4] = {0.f, 0.f, 0.f, 0.f};
            uint32_t bK = sb + AK_OFF +
                (uint32_t)((g * 16 + (q4 >> 1) * 8 + rr) * 272 + (q4 & 1) * 16);
#pragma unroll
            for (int p = 0; p < 3; p++) {
                int ao = (p == 2) ? 128 : 0;
                int bo = (p == 1) ? 128 : 0;
#pragma unroll
                for (int kk = 0; kk < 4; kk++) {
                    uint32_t af[4];
                    LDSM4(af[0], af[1], af[2], af[3], aQ + ao + kk * 32);
                    uint32_t t0, t1, t2, t3;
                    LDSM4(t0, t1, t2, t3, bK + bo + kk * 32);
                    uint32_t b0[2] = {t0, t1}, b1[2] = {t2, t3};
                    MMA16816(c0, af, b0);
                    MMA16816(c1, af, b1);
                }
            }
            int r = lane >> 2, cc = (lane & 3) * 2;
            int n0 = g * 16;
            SF[r * 160 + n0 + cc]           = c0[0];
            SF[r * 160 + n0 + cc + 1]       = c0[1];
            SF[(r + 8) * 160 + n0 + cc]     = c0[2];
            SF[(r + 8) * 160 + n0 + cc + 1] = c0[3];
            SF[r * 160 + n0 + 8 + cc]           = c1[0];
            SF[r * 160 + n0 + 8 + cc + 1]       = c1[1];
            SF[(r + 8) * 160 + n0 + 8 + cc]     = c1[2];
            SF[(r + 8) * 160 + n0 + 8 + cc + 1] = c1[3];
        }
        __syncthreads();
        // ---- double softmax: warp w -> rows 2w, 2w+1 ----
#pragma unroll
        for (int rs = 0; rs < 2; rs++) {
            float* p = SF + (w * 2 + rs) * 160;
            float v[5];
            int cnt = 0;
            float mx = -1e30f;
            for (int j = lane; j < SEQ; j += 32) { v[cnt] = p[j]; mx = fmaxf(mx, v[cnt]); cnt++; }
#pragma unroll
            for (int o = 16; o; o >>= 1) mx = fmaxf(mx, __shfl_xor_sync(0xffffffffu, mx, o));
            float s = 0.f;
            for (int c = 0; c < cnt; c++) { v[c] = __expf(v[c] - mx); s += v[c]; }
#pragma unroll
            for (int o = 16; o; o >>= 1) s += __shfl_xor_sync(0xffffffffu, s, o);
            float inv = 1.0f / s;
            mx = -1e30f;
            for (int c = 0; c < cnt; c++) { v[c] *= inv; mx = fmaxf(mx, v[c]); }
#pragma unroll
            for (int o = 16; o; o >>= 1) mx = fmaxf(mx, __shfl_xor_sync(0xffffffffu, mx, o));
            s = 0.f;
            for (int c = 0; c < cnt; c++) { v[c] = __expf(v[c] - mx); s += v[c]; }
#pragma unroll
            for (int o = 16; o; o >>= 1) s += __shfl_xor_sync(0xffffffffu, s, o);
            inv = 1.0f / s;
            cnt = 0;
            for (int j = lane; j < SEQ; j += 32) { p[j] = v[cnt] * inv; cnt++; }
        }
        __syncthreads();
        // ---- convert S -> split-bf16 ----
        for (int idx = t; idx < 16 * 144; idx += 256) {
            int r = idx / 144, cc = idx - r * 144;
            __nv_bfloat16 hi, lo;
            split_bf16(SF[r * 160 + cc], hi, lo);
            *(__nv_bfloat16*)(smc + ASB_OFF + r * 592 + cc * 2) = hi;
            *(__nv_bfloat16*)(smc + ASB_OFF + r * 592 + 288 + cc * 2) = lo;
        }
        __syncthreads();
        // ---- O = S @ v (mma, 3-pass) ----
        {
            float c0[4] = {0.f, 0.f, 0.f, 0.f};
            uint32_t bV = sb + AV_OFF +
                (uint32_t)((w * 8 + (lane & 7)) * 592 + ((lane >> 3) & 1) * 16);
#pragma unroll
            for (int p = 0; p < 3; p++) {
                int ao = (p == 2) ? 288 : 0;
                int bo = (p == 1) ? 288 : 0;
#pragma unroll
                for (int kk = 0; kk < 9; kk++) {
                    uint32_t af[4];
                    LDSM4(af[0], af[1], af[2], af[3], aS + ao + kk * 32);
                    uint32_t b0[2];
                    LDSM2(b0[0], b0[1], bV + bo + kk * 32);
                    MMA16816(c0, af, b0);
                }
            }
            int r = lane >> 2, cc = (lane & 3) * 2;
            int col = h * HDIM + w * 8 + cc;
#pragma unroll
            for (int half = 0; half < 2; half++) {
                int m = r0m + r + half * 8;
                if (m < SEQ) {
                    float va = c0[half * 2], vb = c0[half * 2 + 1];
                    __nv_bfloat16 h0, l0, h1, l1;
                    split_bf16(va, h0, l0);
                    split_bf16(vb, h1, l1);
                    __nv_bfloat16* dst = a2 + ((size_t)b * SEQ + m) * 1024 + col;
                    __nv_bfloat162 ph; ph.x = h0; ph.y = h1;
                    __nv_bfloat162 pl; pl.x = l0; pl.y = l1;
                    *(__nv_bfloat162*)dst = ph;
                    *(__nv_bfloat162*)(dst + 512) = pl;
                }
            }
        }
    }
}

// ---------------- weight conversion (interleave option for W0) -------------
__global__ void convB_kernel(const float* __restrict__ W, __nv_bfloat16* __restrict__ dst,
                             int K, int N, int Kpad, size_t wStride, size_t dStride,
                             int interleave) {
    __shared__ float t[32][33];
    const float* Wl = W + blockIdx.z * wStride;
    __nv_bfloat16* dl = dst + blockIdx.z * dStride;
    int k0 = blockIdx.x * 32, n0 = blockIdx.y * 32;
    int tx = threadIdx.x, ty = threadIdx.y;
#pragma unroll
    for (int i = 0; i < 4; i++) {
        int k = k0 + ty + i * 8, n = n0 + tx;
        int nsrc = interleave ? ((n >> 1) + (n & 1) * NHID) : n;
        t[ty + i * 8][tx] = (k < K && n < N) ? Wl[(size_t)k * N + nsrc] : 0.f;
    }
    __syncthreads();
#pragma unroll
    for (int i = 0; i < 4; i++) {
        int n = n0 + ty + i * 8, k = k0 + tx;
        float v = t[tx][ty + i * 8];
        __nv_bfloat16 hi, lo; split_bf16(v, hi, lo);
        dl[(size_t)n * 2 * Kpad + k] = hi;
        dl[(size_t)n * 2 * Kpad + Kpad + k] = lo;
    }
}

// ---------------- A conversion (layer 0 only) ------------------------------
__global__ void convA_kernel(const float* __restrict__ src, __nv_bfloat16* __restrict__ dst) {
    int m = blockIdx.x;
    const float* s = src + (size_t)m * EMBD;
    __nv_bfloat16* d = dst + (size_t)m * 1024;
    for (int k = threadIdx.x; k < 512; k += 128) {
        __nv_bfloat16 hi, lo; split_bf16(s[k], hi, lo);
        d[k] = hi; d[512 + k] = lo;
    }
}

// ---------------- tokenizer ------------------------------------------------
__global__ void tokenizer_kernel(const float* __restrict__ x,
                                 const float* __restrict__ tok_w,
                                 const float* __restrict__ tok_b,
                                 const float* __restrict__ cat_emb,
                                 float* __restrict__ h) {
    int t = blockIdx.x;
    int b = t / SEQ, s = t % SEQ;
    int e0 = threadIdx.x;
    const float* src;
    float scale = 1.0f;
    const float* brow = nullptr;
    if (s == 0) {
        src = tok_w;
    } else if (s <= NCONT) {
        src = tok_w + (size_t)s * EMBD;
        scale = x[(size_t)b * (NCAT + NCONT) + NCAT + (s - 1)];
        brow = tok_b + (size_t)(s - 1) * EMBD;
    } else {
        int c = s - (NCONT + 1);
        int idx = (int)x[(size_t)b * (NCAT + NCONT) + c] + 100 * c;
        src = cat_emb + (size_t)idx * EMBD;
        brow = tok_b + (size_t)(s - 1) * EMBD;
    }
    float* dst = h + (size_t)t * EMBD;
#pragma unroll
    for (int i = 0; i < 4; i++) {
        int e = e0 + i * 128;
        float v = src[e] * scale;
        if (brow) v += brow[e];
        dst[e] = v;
    }
}

// ---------------- layernorm -> bf16 hi/lo ----------------------------------
__global__ void ln_conv_kernel(const float* __restrict__ in,
                               const float* __restrict__ g,
                               const float* __restrict__ b,
                               __nv_bfloat16* __restrict__ out) {
    int row = blockIdx.x * 8 + threadIdx.y;
    if (row >= NTOK) return;
    const float* p = in + (size_t)row * EMBD;
    int lane = threadIdx.x;
    float v[16];
    float s = 0.f;
#pragma unroll
    for (int i = 0; i < 16; i++) { v[i] = p[lane + 32 * i]; s += v[i]; }
#pragma unroll
    for (int o = 16; o; o >>= 1) s += __shfl_xor_sync(0xffffffffu, s, o);
    float mean = s * (1.0f / EMBD);
    float vs = 0.f;
#pragma unroll
    for (int i = 0; i < 16; i++) { float d = v[i] - mean; vs += d * d; }
#pragma unroll
    for (int o = 16; o; o >>= 1) vs += __shfl_xor_sync(0xffffffffu, vs, o);
    float inv = rsqrtf(vs * (1.0f / EMBD) + 1e-5f);
    __nv_bfloat16* qo = out + (size_t)row * 1024;
#pragma unroll
    for (int i = 0; i < 16; i++) {
        int e = lane + 32 * i;
        float y = (v[i] - mean) * inv * g[e] + b[e];
        __nv_bfloat16 hi, lo; split_bf16(y, hi, lo);
        qo[e] = hi; qo[512 + e] = lo;
    }
}

// ---------------- extract CLS ----------------------------------------------
__global__ void extract_kernel(const float* __restrict__ h, float* __restrict__ out) {
    int b = blockIdx.x;
    int e = threadIdx.x;
    out[(size_t)b * EMBD + e] = h[(size_t)b * SEQ * EMBD + e];
}

// ---------------- host -----------------------------------------------------
extern "C" void kernel_launch(void* const* d_in, const int* in_sizes, int n_in,
                              void* d_out, int out_size) {
    (void)in_sizes; (void)n_in; (void)out_size;
    const float* x       = (const float*)d_in[0];
    const float* tok_w   = (const float*)d_in[1];
    const float* tok_b   = (const float*)d_in[2];
    const float* cat_emb = (const float*)d_in[3];
    const float* Wqkv    = (const float*)d_in[4];
    const float* bqkv    = (const float*)d_in[5];
    const float* Wout    = (const float*)d_in[6];
    const float* bout    = (const float*)d_in[7];
    const float* W0      = (const float*)d_in[8];
    const float* b0      = (const float*)d_in[9];
    const float* W1      = (const float*)d_in[10];
    const float* b1      = (const float*)d_in[11];
    const float* ln0_g   = (const float*)d_in[12];
    const float* ln0_b   = (const float*)d_in[13];
    const float* ln1_g   = (const float*)d_in[14];
    const float* ln1_b   = (const float*)d_in[15];
    float* out = (float*)d_out;

    float *ph, *pqkv;
    __nv_bfloat16 *pa2, *pr, *pb2, *pqk;
    cudaGetSymbolAddress((void**)&ph, g_h);
    cudaGetSymbolAddress((void**)&pqkv, g_qkv);
    cudaGetSymbolAddress((void**)&pa2, g_a2);
    cudaGetSymbolAddress((void**)&pr, g_r);
    cudaGetSymbolAddress((void**)&pb2, g_b2);
    cudaGetSymbolAddress((void**)&pqk, g_qk);

    cudaFuncSetAttribute(gemm_mma, cudaFuncAttributeMaxDynamicSharedMemorySize, GEMM_SMEM);
    cudaFuncSetAttribute(attn_mma, cudaFuncAttributeMaxDynamicSharedMemorySize, ATT_SMEM);

    // zero reglu operand once (pads stay zero; data cols overwritten per layer)
    cudaMemsetAsync(pr, 0, (size_t)NTOK * 1408 * sizeof(__nv_bfloat16));

    // weight conversion, batched over all layers
    {
        __nv_bfloat16* bq  = pb2;
        __nv_bfloat16* bo  = pb2 + B2_QKV_SZ;
        __nv_bfloat16* b0p = pb2 + B2_QKV_SZ + B2_WOUT_SZ;
        __nv_bfloat16* b1p = pb2 + B2_QKV_SZ + B2_WOUT_SZ + B2_W0_SZ;
        convB_kernel<<<dim3(16, 48, NDEPTH), dim3(32, 8)>>>(
            Wqkv, bq, 512, 1536, 512, (size_t)EMBD * QKVN, B2_LAYER, 0);
        convB_kernel<<<dim3(16, 16, NDEPTH), dim3(32, 8)>>>(
            Wout, bo, 512, 512, 512, (size_t)EMBD * EMBD, B2_LAYER, 0);
        convB_kernel<<<dim3(16, 48, NDEPTH), dim3(32, 8)>>>(
            W0, b0p, 512, HID2, 512, (size_t)EMBD * HID2, B2_LAYER, 1);
        convB_kernel<<<dim3(22, 16, NDEPTH), dim3(32, 8)>>>(
            W1, b1p, NHID, 512, KPAD_H, (size_t)NHID * EMBD, B2_LAYER, 0);
    }

    tokenizer_kernel<<<NTOK, 128>>>(x, tok_w, tok_b, cat_emb, ph);

    for (int L = 0; L < NDEPTH; L++) {
        __nv_bfloat16* bq  = pb2 + (size_t)L * B2_LAYER;
        __nv_bfloat16* bo  = bq + B2_QKV_SZ;
        __nv_bfloat16* b0p = bo + B2_WOUT_SZ;
        __nv_bfloat16* b1p = b0p + B2_W0_SZ;

        if (L == 0) {
            convA_kernel<<<NTOK, 128>>>(ph, pa2);
        } else {
            ln_conv_kernel<<<NTOK / 8, dim3(32, 8)>>>(ph, ln0_g + L * EMBD, ln0_b + L * EMBD, pa2);
        }
        // QKV: q,k split-bf16 -> pqk ; v fp32 -> pqkv
        gemm_mma<<<dim3(129, 12), 256, GEMM_SMEM>>>(pa2, bq, bqkv + (size_t)L * QKVN,
                                                    nullptr, pqkv, pqk, QKVN, QKVN, KPAD_E, 3);
        attn_mma<<<NBH, 256, ATT_SMEM>>>(pqk, pqkv, pa2);
        gemm_mma<<<dim3(129, 4), 256, GEMM_SMEM>>>(pa2, bo, bout + (size_t)L * EMBD,
                                                   ph, ph, nullptr, EMBD, EMBD, KPAD_E, 1);
        ln_conv_kernel<<<NTOK / 8, dim3(32, 8)>>>(ph, ln1_g + L * EMBD, ln1_b + L * EMBD, pa2);
        // W0 + ReGLU fused (interleaved columns) -> pr
        gemm_mma<<<dim3(129, 11), 256, GEMM_SMEM>>>(pa2, b0p, b0 + (size_t)L * HID2,
                                                    nullptr, nullptr, pr, HID2, 0, KPAD_E, 2);
        gemm_mma<<<dim3(129, 4), 256, GEMM_SMEM>>>(pr, b1p, b1 + (size_t)L * EMBD,
                                                   ph, ph, nullptr, EMBD, EMBD, KPAD_H, 1);
    }
    extract_kernel<<<BSZ, EMBD>>>(ph, out);
}

// round 14
// speedup vs baseline: 1.0314x; 1.0314x over previous
#include <cuda_runtime.h>
#include <cuda_bf16.h>
#include <cstdint>
#include <math.h>

#define EMBD 512
#define NHEADS 8
#define HDIM 64
#define NDEPTH 6
#define NCONT 100
#define NCAT 28
#define NHID 682
#define BSZ 128
#define SEQ 129
#define NTOK (BSZ*SEQ)      /* 16512 */
#define QKVN (3*EMBD)       /* 1536  */
#define HID2 (2*NHID)       /* 1364  */
#define NBH (BSZ*NHEADS)    /* 1024  */

#define KPAD_E 512
#define KPAD_H 704
#define W0_NPAD 1536

// ---------------- scratch (device globals) ---------------------------------
__device__ float g_h[NTOK*EMBD];
__device__ float g_qkv[NTOK*QKVN];
__device__ __nv_bfloat16 g_a2[(size_t)NTOK*1024];            // EMB-K operand
__device__ __nv_bfloat16 g_r[(size_t)NTOK*1408];             // reglu operand (Kpad=704)
#define B2_QKV_SZ ((size_t)1536*1024)
#define B2_WOUT_SZ ((size_t)512*1024)
#define B2_W0_SZ ((size_t)W0_NPAD*1024)
#define B2_W1_SZ ((size_t)512*1408)
#define B2_LAYER (B2_QKV_SZ+B2_WOUT_SZ+B2_W0_SZ+B2_W1_SZ)
__device__ __nv_bfloat16 g_b2[B2_LAYER*NDEPTH];

// ---------------- helpers ---------------------------------------------------
__device__ __forceinline__ uint32_t smem_u32(const void* p) {
    uint32_t a;
    asm("{ .reg .u64 t; cvta.to.shared.u64 t, %1; cvt.u32.u64 %0, t; }" : "=r"(a) : "l"(p));
    return a;
}
#define LDSM4(r0, r1, r2, r3, addr) \
    asm volatile("ldmatrix.sync.aligned.m8n8.x4.shared.b16 {%0,%1,%2,%3}, [%4];" \
        : "=r"(r0), "=r"(r1), "=r"(r2), "=r"(r3) : "r"(addr))
#define LDSM2(r0, r1, addr) \
    asm volatile("ldmatrix.sync.aligned.m8n8.x2.shared.b16 {%0,%1}, [%2];" \
        : "=r"(r0), "=r"(r1) : "r"(addr))
#define MMA16816(d, a, b) \
    asm volatile("mma.sync.aligned.m16n8k16.row.col.f32.bf16.bf16.f32 " \
        "{%0,%1,%2,%3},{%4,%5,%6,%7},{%8,%9},{%0,%1,%2,%3};" \
        : "+f"((d)[0]), "+f"((d)[1]), "+f"((d)[2]), "+f"((d)[3]) \
        : "r"((a)[0]), "r"((a)[1]), "r"((a)[2]), "r"((a)[3]), "r"((b)[0]), "r"((b)[1]))
#define CPA16(s, g) \
    asm volatile("cp.async.cg.shared.global [%0], [%1], 16;" :: "r"(s), "l"(g))
#define CPA_COMMIT asm volatile("cp.async.commit_group;" ::: "memory")
#define CPA_WAIT(n) asm volatile("cp.async.wait_group %0;" :: "n"(n) : "memory")

__device__ __forceinline__ void split_bf16(float v, __nv_bfloat16& hi, __nv_bfloat16& lo) {
    hi = __float2bfloat16(v);
    lo = __float2bfloat16(v - __bfloat162float(hi));
}

// ---------------- HMMA GEMM: 3-pass bf16 split -----------------------------
// mode 0: C = acc + bias ; mode 1: += res ; mode 2: reglu(acc+bias) -> Rout
#define PITCH 144
#define ABUF (128*PITCH)
#define BBUF (128*PITCH)
#define BOFF (3*ABUF)
#define GEMM_SMEM (3*(ABUF+BBUF))     /* 110592 B */
__global__ void __launch_bounds__(256, 2)
gemm_mma(const __nv_bfloat16* __restrict__ A2, const __nv_bfloat16* __restrict__ B2,
         const float* __restrict__ bias, const float* __restrict__ res,
         float* __restrict__ C, __nv_bfloat16* __restrict__ Rout,
         int Nact, int Cs, int Kpad, int mode) {
    extern __shared__ __nv_bfloat16 dsm[];
    const uint32_t sbase = smem_u32(dsm);
    const int tid = threadIdx.x, lane = tid & 31, wid = tid >> 5;
    const int wm = wid & 1, wn = wid >> 1;
    const int m0 = blockIdx.x * 128, n0 = blockIdx.y * 128;
    const int sA2 = 2 * Kpad;
    const int KC = Kpad >> 6;
    const int nsteps = 3 * KC;

    float acc[4][4][4];
#pragma unroll
    for (int a = 0; a < 4; a++)
#pragma unroll
        for (int b = 0; b < 4; b++)
#pragma unroll
            for (int c = 0; c < 4; c++) acc[a][b][c] = 0.f;

    const int rT = tid >> 3, cT = tid & 7;
    const uint32_t sA0 = sbase + rT * PITCH + cT * 16;
    const uint32_t sB0 = sbase + BOFF + rT * PITCH + cT * 16;
    const __nv_bfloat16* gA0 = A2 + (size_t)(m0 + rT) * sA2 + cT * 8;
    const __nv_bfloat16* gB0 = B2 + (size_t)(n0 + rT) * sA2 + cT * 8;

#define ISSUE(i) do { \
    int pass = ((i) >= 2 * KC) ? 2 : (((i) >= KC) ? 1 : 0); \
    int kc = (i) - pass * KC; \
    int aO = ((pass == 2) ? Kpad : 0) + kc * 64; \
    int bO = ((pass == 1) ? Kpad : 0) + kc * 64; \
    int bufi = (i) % 3; \
    uint32_t sa = sA0 + bufi * ABUF; \
    uint32_t sb = sB0 + bufi * BBUF; \
    CPA16(sa,             gA0 + aO); \
    CPA16(sa + 32*PITCH,  gA0 + aO + (size_t)32 * sA2); \
    CPA16(sa + 64*PITCH,  gA0 + aO + (size_t)64 * sA2); \
    CPA16(sa + 96*PITCH,  gA0 + aO + (size_t)96 * sA2); \
    CPA16(sb,             gB0 + bO); \
    CPA16(sb + 32*PITCH,  gB0 + bO + (size_t)32 * sA2); \
    CPA16(sb + 64*PITCH,  gB0 + bO + (size_t)64 * sA2); \
    CPA16(sb + 96*PITCH,  gB0 + bO + (size_t)96 * sA2); \
    CPA_COMMIT; \
} while (0)

    const int q = lane >> 3, rr = lane & 7;
    const uint32_t aBase = sbase +
        (uint32_t)((wm * 64 + (q & 1) * 8 + rr) * PITCH + (q >> 1) * 16);
    const uint32_t bBase = sbase + BOFF +
        (uint32_t)((wn * 32 + (q >> 1) * 8 + rr) * PITCH + (q & 1) * 16);

    ISSUE(0);
    ISSUE(1);

    for (int i = 0; i < nsteps; i++) {
        if (i == nsteps - 1) CPA_WAIT(0); else CPA_WAIT(1);
        __syncthreads();
        if (i + 2 < nsteps) ISSUE(i + 2);
        const int buf = i % 3;
        const uint32_t aB = aBase + buf * ABUF;
        const uint32_t bB = bBase + buf * BBUF;
#pragma unroll
        for (int kk = 0; kk < 4; kk++) {
            uint32_t af[4][4];
#pragma unroll
            for (int mi = 0; mi < 4; mi++)
                LDSM4(af[mi][0], af[mi][1], af[mi][2], af[mi][3],
                      aB + mi * (16 * PITCH) + kk * 32);
            uint32_t bfr[4][2];
#pragma unroll
            for (int g = 0; g < 2; g++) {
                uint32_t t0, t1, t2, t3;
                LDSM4(t0, t1, t2, t3, bB + g * (16 * PITCH) + kk * 32);
                bfr[2 * g][0] = t0;     bfr[2 * g][1] = t1;
                bfr[2 * g + 1][0] = t2; bfr[2 * g + 1][1] = t3;
            }
#pragma unroll
            for (int mi = 0; mi < 4; mi++)
#pragma unroll
                for (int ni = 0; ni < 4; ni++)
                    MMA16816(acc[mi][ni], af[mi], bfr[ni]);
        }
    }

    // epilogue
    if (mode == 2) {
#pragma unroll
        for (int mi = 0; mi < 4; mi++) {
            int r0 = m0 + wm * 64 + mi * 16 + (lane >> 2);
            __nv_bfloat16* d0 = Rout + (size_t)r0 * 1408;
            __nv_bfloat16* d1 = Rout + (size_t)(r0 + 8) * 1408;
#pragma unroll
            for (int ni = 0; ni < 4; ni++) {
                int c0 = n0 + wn * 32 + ni * 8 + (lane & 3) * 2;
                if (c0 < HID2) {
                    int j = c0 >> 1;
                    float ba = bias[j], bb = bias[NHID + j];
                    float v0 = (acc[mi][ni][0] + ba) * fmaxf(acc[mi][ni][1] + bb, 0.f);
                    float v1 = (acc[mi][ni][2] + ba) * fmaxf(acc[mi][ni][3] + bb, 0.f);
                    __nv_bfloat16 hi, lo;
                    split_bf16(v0, hi, lo); d0[j] = hi; d0[704 + j] = lo;
                    split_bf16(v1, hi, lo); d1[j] = hi; d1[704 + j] = lo;
                }
            }
        }
    } else {
#pragma unroll
        for (int mi = 0; mi < 4; mi++) {
            int r0 = m0 + wm * 64 + mi * 16 + (lane >> 2);
            float* cr0 = C + (size_t)r0 * Cs;
            float* cr1 = C + (size_t)(r0 + 8) * Cs;
            const float* rr0 = res + (size_t)r0 * Cs;
            const float* rr1 = res + (size_t)(r0 + 8) * Cs;
#pragma unroll
            for (int ni = 0; ni < 4; ni++) {
                int c0 = n0 + wn * 32 + ni * 8 + (lane & 3) * 2;
                if (c0 < Nact) {
                    float2 bv = *(const float2*)&bias[c0];
                    float2 v01 = make_float2(acc[mi][ni][0] + bv.x, acc[mi][ni][1] + bv.y);
                    float2 v23 = make_float2(acc[mi][ni][2] + bv.x, acc[mi][ni][3] + bv.y);
                    if (mode == 1) {
                        float2 ra = *(const float2*)&rr0[c0];
                        float2 rb = *(const float2*)&rr1[c0];
                        v01.x += ra.x; v01.y += ra.y;
                        v23.x += rb.x; v23.y += rb.y;
                    }
                    *(float2*)&cr0[c0] = v01;
                    *(float2*)&cr1[c0] = v23;
                }
            }
        }
    }
}

// ---------------- tensor-core fused attention ------------------------------
// Padded tokens T=144. smem layout (bytes):
//   QP  @ 0      : 16 rows x 272   (q hi|lo)          4352
//   KP  @ 4352   : 144 rows x 272  (k hi|lo)         39168
//   VT  @ 43520  : 64 rows x 592   (v^T hi|lo)       37888
//   SB  @ 81408  : 16 rows x 592   (S hi|lo)          9472
//   SF  @ 90880  : 16 rows x 160 fp32                10240
#define AQ_OFF 0
#define AK_OFF 4352
#define AV_OFF 43520
#define ASB_OFF 81408
#define ASF_OFF 90880
#define ATT_SMEM 101120
__global__ void __launch_bounds__(256, 2)
attn_mma(const float* __restrict__ qkv, __nv_bfloat16* __restrict__ a2) {
    extern __shared__ char smc[];
    const uint32_t sb = smem_u32(smc);
    float* SF = (float*)(smc + ASF_OFF);
    const int bh = blockIdx.x;
    const int b = bh >> 3, h = bh & 7;
    const float* base = qkv + (size_t)b * SEQ * QKVN + h * (3 * HDIM);
    const int t = threadIdx.x, lane = t & 31, w = t >> 5;
    const float scale = 22.62741699796952f;   // sqrt(512)

    // load k, v^T split-bf16, zero-padded tokens 129..143
    for (int idx = t; idx < 144 * 64; idx += 256) {
        int tok = idx >> 6, d = idx & 63;
        float kv = 0.f, vv = 0.f;
        if (tok < SEQ) {
            const float* row = base + (size_t)tok * QKVN;
            kv = row[HDIM + d];
            vv = row[2 * HDIM + d];
        }
        __nv_bfloat16 hi, lo;
        split_bf16(kv, hi, lo);
        *(__nv_bfloat16*)(smc + AK_OFF + tok * 272 + d * 2) = hi;
        *(__nv_bfloat16*)(smc + AK_OFF + tok * 272 + 128 + d * 2) = lo;
        split_bf16(vv, hi, lo);
        *(__nv_bfloat16*)(smc + AV_OFF + d * 592 + tok * 2) = hi;
        *(__nv_bfloat16*)(smc + AV_OFF + d * 592 + 288 + tok * 2) = lo;
    }

    const int q4 = lane >> 3, rr = lane & 7;
    const uint32_t aQ = sb + AQ_OFF +
        (uint32_t)(((q4 & 1) * 8 + rr) * 272 + (q4 >> 1) * 16);
    const uint32_t aS = sb + ASB_OFF +
        (uint32_t)(((q4 & 1) * 8 + rr) * 592 + (q4 >> 1) * 16);

    for (int blk = 0; blk < 9; blk++) {
        const int r0m = blk * 16;
        __syncthreads();   // previous block fully consumed QP/SF/SB
        // ---- load q block, pre-scaled, split ----
        {
            int r = t >> 4, d0 = (t & 15) * 4;
            int m = r0m + r;
            float4 qv = make_float4(0.f, 0.f, 0.f, 0.f);
            if (m < SEQ) qv = *(const float4*)(base + (size_t)m * QKVN + d0);
            float vals[4] = {qv.x * scale, qv.y * scale, qv.z * scale, qv.w * scale};
            char* qd = smc + AQ_OFF + r * 272;
#pragma unroll
            for (int i = 0; i < 4; i++) {
                __nv_bfloat16 hi, lo;
                split_bf16(vals[i], hi, lo);
                *(__nv_bfloat16*)(qd + (d0 + i) * 2) = hi;
                *(__nv_bfloat16*)(qd + 128 + (d0 + i) * 2) = lo;
            }
        }
        __syncthreads();
        // ---- S = q @ k^T (mma, 3-pass) ----
        for (int g = w; g < 9; g += 8) {
            float c0[4] = {0.f, 0.f, 0.f, 0.f};
            float c1[4] = {0.f, 0.f, 0.f, 0.f};
            uint32_t bK = sb + AK_OFF +
                (uint32_t)((g * 16 + (q4 >> 1) * 8 + rr) * 272 + (q4 & 1) * 16);
#pragma unroll
            for (int p = 0; p < 3; p++) {
                int ao = (p == 2) ? 128 : 0;
                int bo = (p == 1) ? 128 : 0;
#pragma unroll
                for (int kk = 0; kk < 4; kk++) {
                    uint32_t af[4];
                    LDSM4(af[0], af[1], af[2], af[3], aQ + ao + kk * 32);
                    uint32_t t0, t1, t2, t3;
                    LDSM4(t0, t1, t2, t3, bK + bo + kk * 32);
                    uint32_t b0[2] = {t0, t1}, b1[2] = {t2, t3};
                    MMA16816(c0, af, b0);
                    MMA16816(c1, af, b1);
                }
            }
            int r = lane >> 2, cc = (lane & 3) * 2;
            int n0 = g * 16;
            SF[r * 160 + n0 + cc]           = c0[0];
            SF[r * 160 + n0 + cc + 1]       = c0[1];
            SF[(r + 8) * 160 + n0 + cc]     = c0[2];
            SF[(r + 8) * 160 + n0 + cc + 1] = c0[3];
            SF[r * 160 + n0 + 8 + cc]           = c1[0];
            SF[r * 160 + n0 + 8 + cc + 1]       = c1[1];
            SF[(r + 8) * 160 + n0 + 8 + cc]     = c1[2];
            SF[(r + 8) * 160 + n0 + 8 + cc + 1] = c1[3];
        }
        __syncthreads();
        // ---- double softmax: warp w -> rows 2w, 2w+1 ----
#pragma unroll
        for (int rs = 0; rs < 2; rs++) {
            float* p = SF + (w * 2 + rs) * 160;
            float v[5];
            int cnt = 0;
            float mx = -1e30f;
            for (int j = lane; j < SEQ; j += 32) { v[cnt] = p[j]; mx = fmaxf(mx, v[cnt]); cnt++; }
#pragma unroll
            for (int o = 16; o; o >>= 1) mx = fmaxf(mx, __shfl_xor_sync(0xffffffffu, mx, o));
            float s = 0.f;
            for (int c = 0; c < cnt; c++) { v[c] = __expf(v[c] - mx); s += v[c]; }
#pragma unroll
            for (int o = 16; o; o >>= 1) s += __shfl_xor_sync(0xffffffffu, s, o);
            float inv = 1.0f / s;
            mx = -1e30f;
            for (int c = 0; c < cnt; c++) { v[c] *= inv; mx = fmaxf(mx, v[c]); }
#pragma unroll
            for (int o = 16; o; o >>= 1) mx = fmaxf(mx, __shfl_xor_sync(0xffffffffu, mx, o));
            s = 0.f;
            for (int c = 0; c < cnt; c++) { v[c] = __expf(v[c] - mx); s += v[c]; }
#pragma unroll
            for (int o = 16; o; o >>= 1) s += __shfl_xor_sync(0xffffffffu, s, o);
            inv = 1.0f / s;
            cnt = 0;
            for (int j = lane; j < SEQ; j += 32) { p[j] = v[cnt] * inv; cnt++; }
        }
        __syncthreads();
        // ---- convert S -> split-bf16 (cols 0..143; pads are 0) ----
        for (int idx = t; idx < 16 * 144; idx += 256) {
            int r = idx / 144, cc = idx - r * 144;
            __nv_bfloat16 hi, lo;
            split_bf16(SF[r * 160 + cc], hi, lo);
            *(__nv_bfloat16*)(smc + ASB_OFF + r * 592 + cc * 2) = hi;
            *(__nv_bfloat16*)(smc + ASB_OFF + r * 592 + 288 + cc * 2) = lo;
        }
        __syncthreads();
        // ---- O = S @ v (mma, 3-pass) ----
        {
            float c0[4] = {0.f, 0.f, 0.f, 0.f};
            uint32_t bV = sb + AV_OFF +
                (uint32_t)((w * 8 + (lane & 7)) * 592 + ((lane >> 3) & 1) * 16);
#pragma unroll
            for (int p = 0; p < 3; p++) {
                int ao = (p == 2) ? 288 : 0;
                int bo = (p == 1) ? 288 : 0;
#pragma unroll
                for (int kk = 0; kk < 9; kk++) {
                    uint32_t af[4];
                    LDSM4(af[0], af[1], af[2], af[3], aS + ao + kk * 32);
                    uint32_t b0[2];
                    LDSM2(b0[0], b0[1], bV + bo + kk * 32);
                    MMA16816(c0, af, b0);
                }
            }
            int r = lane >> 2, cc = (lane & 3) * 2;
            int col = h * HDIM + w * 8 + cc;
#pragma unroll
            for (int half = 0; half < 2; half++) {
                int m = r0m + r + half * 8;
                if (m < SEQ) {
                    float va = c0[half * 2], vb = c0[half * 2 + 1];
                    __nv_bfloat16 h0, l0, h1, l1;
                    split_bf16(va, h0, l0);
                    split_bf16(vb, h1, l1);
                    __nv_bfloat16* dst = a2 + ((size_t)b * SEQ + m) * 1024 + col;
                    __nv_bfloat162 ph; ph.x = h0; ph.y = h1;
                    __nv_bfloat162 pl; pl.x = l0; pl.y = l1;
                    *(__nv_bfloat162*)dst = ph;
                    *(__nv_bfloat162*)(dst + 512) = pl;
                }
            }
        }
    }
}

// ---------------- weight conversion (interleave option for W0) -------------
__global__ void convB_kernel(const float* __restrict__ W, __nv_bfloat16* __restrict__ dst,
                             int K, int N, int Kpad, size_t wStride, size_t dStride,
                             int interleave) {
    __shared__ float t[32][33];
    const float* Wl = W + blockIdx.z * wStride;
    __nv_bfloat16* dl = dst + blockIdx.z * dStride;
    int k0 = blockIdx.x * 32, n0 = blockIdx.y * 32;
    int tx = threadIdx.x, ty = threadIdx.y;
#pragma unroll
    for (int i = 0; i < 4; i++) {
        int k = k0 + ty + i * 8, n = n0 + tx;
        int nsrc = interleave ? ((n >> 1) + (n & 1) * NHID) : n;
        t[ty + i * 8][tx] = (k < K && n < N) ? Wl[(size_t)k * N + nsrc] : 0.f;
    }
    __syncthreads();
#pragma unroll
    for (int i = 0; i < 4; i++) {
        int n = n0 + ty + i * 8, k = k0 + tx;
        float v = t[tx][ty + i * 8];
        __nv_bfloat16 hi, lo; split_bf16(v, hi, lo);
        dl[(size_t)n * 2 * Kpad + k] = hi;
        dl[(size_t)n * 2 * Kpad + Kpad + k] = lo;
    }
}

// ---------------- tokenizer (also emits split-bf16 a2 for layer 0) ---------
__global__ void tokenizer_kernel(const float* __restrict__ x,
                                 const float* __restrict__ tok_w,
                                 const float* __restrict__ tok_b,
                                 const float* __restrict__ cat_emb,
                                 float* __restrict__ h,
                                 __nv_bfloat16* __restrict__ a2) {
    int t = blockIdx.x;
    int b = t / SEQ, s = t % SEQ;
    int e0 = threadIdx.x;
    const float* src;
    float scale = 1.0f;
    const float* brow = nullptr;
    if (s == 0) {
        src = tok_w;
    } else if (s <= NCONT) {
        src = tok_w + (size_t)s * EMBD;
        scale = x[(size_t)b * (NCAT + NCONT) + NCAT + (s - 1)];
        brow = tok_b + (size_t)(s - 1) * EMBD;
    } else {
        int c = s - (NCONT + 1);
        int idx = (int)x[(size_t)b * (NCAT + NCONT) + c] + 100 * c;
        src = cat_emb + (size_t)idx * EMBD;
        brow = tok_b + (size_t)(s - 1) * EMBD;
    }
    float* dst = h + (size_t)t * EMBD;
    __nv_bfloat16* da = a2 + (size_t)t * 1024;
#pragma unroll
    for (int i = 0; i < 4; i++) {
        int e = e0 + i * 128;
        float v = src[e] * scale;
        if (brow) v += brow[e];
        dst[e] = v;
        __nv_bfloat16 hi, lo; split_bf16(v, hi, lo);
        da[e] = hi; da[512 + e] = lo;
    }
}

// ---------------- layernorm -> bf16 hi/lo ----------------------------------
__global__ void ln_conv_kernel(const float* __restrict__ in,
                               const float* __restrict__ g,
                               const float* __restrict__ b,
                               __nv_bfloat16* __restrict__ out) {
    int row = blockIdx.x * 8 + threadIdx.y;
    if (row >= NTOK) return;
    const float* p = in + (size_t)row * EMBD;
    int lane = threadIdx.x;
    float v[16];
    float s = 0.f;
#pragma unroll
    for (int i = 0; i < 16; i++) { v[i] = p[lane + 32 * i]; s += v[i]; }
#pragma unroll
    for (int o = 16; o; o >>= 1) s += __shfl_xor_sync(0xffffffffu, s, o);
    float mean = s * (1.0f / EMBD);
    float vs = 0.f;
#pragma unroll
    for (int i = 0; i < 16; i++) { float d = v[i] - mean; vs += d * d; }
#pragma unroll
    for (int o = 16; o; o >>= 1) vs += __shfl_xor_sync(0xffffffffu, vs, o);
    float inv = rsqrtf(vs * (1.0f / EMBD) + 1e-5f);
    __nv_bfloat16* qo = out + (size_t)row * 1024;
#pragma unroll
    for (int i = 0; i < 16; i++) {
        int e = lane + 32 * i;
        float y = (v[i] - mean) * inv * g[e] + b[e];
        __nv_bfloat16 hi, lo; split_bf16(y, hi, lo);
        qo[e] = hi; qo[512 + e] = lo;
    }
}

// ---------------- extract CLS ----------------------------------------------
__global__ void extract_kernel(const float* __restrict__ h, float* __restrict__ out) {
    int b = blockIdx.x;
    int e = threadIdx.x;
    out[(size_t)b * EMBD + e] = h[(size_t)b * SEQ * EMBD + e];
}

// ---------------- host -----------------------------------------------------
extern "C" void kernel_launch(void* const* d_in, const int* in_sizes, int n_in,
                              void* d_out, int out_size) {
    (void)in_sizes; (void)n_in; (void)out_size;
    const float* x       = (const float*)d_in[0];
    const float* tok_w   = (const float*)d_in[1];
    const float* tok_b   = (const float*)d_in[2];
    const float* cat_emb = (const float*)d_in[3];
    const float* Wqkv    = (const float*)d_in[4];
    const float* bqkv    = (const float*)d_in[5];
    const float* Wout    = (const float*)d_in[6];
    const float* bout    = (const float*)d_in[7];
    const float* W0      = (const float*)d_in[8];
    const float* b0      = (const float*)d_in[9];
    const float* W1      = (const float*)d_in[10];
    const float* b1      = (const float*)d_in[11];
    const float* ln0_g   = (const float*)d_in[12];
    const float* ln0_b   = (const float*)d_in[13];
    const float* ln1_g   = (const float*)d_in[14];
    const float* ln1_b   = (const float*)d_in[15];
    float* out = (float*)d_out;

    float *ph, *pqkv;
    __nv_bfloat16 *pa2, *pr, *pb2;
    cudaGetSymbolAddress((void**)&ph, g_h);
    cudaGetSymbolAddress((void**)&pqkv, g_qkv);
    cudaGetSymbolAddress((void**)&pa2, g_a2);
    cudaGetSymbolAddress((void**)&pr, g_r);
    cudaGetSymbolAddress((void**)&pb2, g_b2);

    cudaFuncSetAttribute(gemm_mma, cudaFuncAttributeMaxDynamicSharedMemorySize, GEMM_SMEM);
    cudaFuncSetAttribute(attn_mma, cudaFuncAttributeMaxDynamicSharedMemorySize, ATT_SMEM);

    // zero reglu operand once (pads stay zero; data cols overwritten per layer)
    cudaMemsetAsync(pr, 0, (size_t)NTOK * 1408 * sizeof(__nv_bfloat16));

    // weight conversion, batched over all layers
    {
        __nv_bfloat16* bq  = pb2;
        __nv_bfloat16* bo  = pb2 + B2_QKV_SZ;
        __nv_bfloat16* b0p = pb2 + B2_QKV_SZ + B2_WOUT_SZ;
        __nv_bfloat16* b1p = pb2 + B2_QKV_SZ + B2_WOUT_SZ + B2_W0_SZ;
        convB_kernel<<<dim3(16, 48, NDEPTH), dim3(32, 8)>>>(
            Wqkv, bq, 512, 1536, 512, (size_t)EMBD * QKVN, B2_LAYER, 0);
        convB_kernel<<<dim3(16, 16, NDEPTH), dim3(32, 8)>>>(
            Wout, bo, 512, 512, 512, (size_t)EMBD * EMBD, B2_LAYER, 0);
        convB_kernel<<<dim3(16, 48, NDEPTH), dim3(32, 8)>>>(
            W0, b0p, 512, HID2, 512, (size_t)EMBD * HID2, B2_LAYER, 1);
        convB_kernel<<<dim3(22, 16, NDEPTH), dim3(32, 8)>>>(
            W1, b1p, NHID, 512, KPAD_H, (size_t)NHID * EMBD, B2_LAYER, 0);
    }

    tokenizer_kernel<<<NTOK, 128>>>(x, tok_w, tok_b, cat_emb, ph, pa2);

    for (int L = 0; L < NDEPTH; L++) {
        __nv_bfloat16* bq  = pb2 + (size_t)L * B2_LAYER;
        __nv_bfloat16* bo  = bq + B2_QKV_SZ;
        __nv_bfloat16* b0p = bo + B2_WOUT_SZ;
        __nv_bfloat16* b1p = b0p + B2_W0_SZ;

        if (L > 0) {
            ln_conv_kernel<<<NTOK / 8, dim3(32, 8)>>>(ph, ln0_g + L * EMBD, ln0_b + L * EMBD, pa2);
        }
        gemm_mma<<<dim3(129, 12), 256, GEMM_SMEM>>>(pa2, bq, bqkv + (size_t)L * QKVN,
                                                    nullptr, pqkv, nullptr, QKVN, QKVN, KPAD_E, 0);
        attn_mma<<<NBH, 256, ATT_SMEM>>>(pqkv, pa2);
        gemm_mma<<<dim3(129, 4), 256, GEMM_SMEM>>>(pa2, bo, bout + (size_t)L * EMBD,
                                                   ph, ph, nullptr, EMBD, EMBD, KPAD_E, 1);
        ln_conv_kernel<<<NTOK / 8, dim3(32, 8)>>>(ph, ln1_g + L * EMBD, ln1_b + L * EMBD, pa2);
        // W0 + ReGLU fused (interleaved columns) -> pr
        gemm_mma<<<dim3(129, 11), 256, GEMM_SMEM>>>(pa2, b0p, b0 + (size_t)L * HID2,
                                                    nullptr, nullptr, pr, HID2, 0, KPAD_E, 2);
        gemm_mma<<<dim3(129, 4), 256, GEMM_SMEM>>>(pr, b1p, b1 + (size_t)L * EMBD,
                                                   ph, ph, nullptr, EMBD, EMBD, KPAD_H, 1);
    }
    extract_kernel<<<BSZ, EMBD>>>(ph, out);
}

// round 15
// speedup vs baseline: 1.0414x; 1.0097x over previous
#include <cuda_runtime.h>
#include <cuda_bf16.h>
#include <cstdint>
#include <math.h>

#define EMBD 512
#define NHEADS 8
#define HDIM 64
#define NDEPTH 6
#define NCONT 100
#define NCAT 28
#define NHID 682
#define BSZ 128
#define SEQ 129
#define NTOK (BSZ*SEQ)      /* 16512 */
#define QKVN (3*EMBD)       /* 1536  */
#define HID2 (2*NHID)       /* 1364  */
#define NBH (BSZ*NHEADS)    /* 1024  */

#define KPAD_E 512
#define KPAD_H 704
#define W0_NPAD 1536

// ---------------- scratch (device globals) ---------------------------------
__device__ float g_h[NTOK*EMBD];
__device__ float g_qkv[NTOK*QKVN];
__device__ __nv_bfloat16 g_a2[(size_t)NTOK*1024];            // EMB-K operand
__device__ __nv_bfloat16 g_r[(size_t)NTOK*1408];             // reglu operand (Kpad=704)
#define B2_QKV_SZ ((size_t)1536*1024)
#define B2_WOUT_SZ ((size_t)512*1024)
#define B2_W0_SZ ((size_t)W0_NPAD*1024)
#define B2_W1_SZ ((size_t)512*1408)
#define B2_LAYER (B2_QKV_SZ+B2_WOUT_SZ+B2_W0_SZ+B2_W1_SZ)
__device__ __nv_bfloat16 g_b2[B2_LAYER*NDEPTH];

// ---------------- helpers ---------------------------------------------------
__device__ __forceinline__ uint32_t smem_u32(const void* p) {
    uint32_t a;
    asm("{ .reg .u64 t; cvta.to.shared.u64 t, %1; cvt.u32.u64 %0, t; }" : "=r"(a) : "l"(p));
    return a;
}
#define LDSM4(r0, r1, r2, r3, addr) \
    asm volatile("ldmatrix.sync.aligned.m8n8.x4.shared.b16 {%0,%1,%2,%3}, [%4];" \
        : "=r"(r0), "=r"(r1), "=r"(r2), "=r"(r3) : "r"(addr))
#define LDSM2(r0, r1, addr) \
    asm volatile("ldmatrix.sync.aligned.m8n8.x2.shared.b16 {%0,%1}, [%2];" \
        : "=r"(r0), "=r"(r1) : "r"(addr))
#define MMA16816(d, a, b) \
    asm volatile("mma.sync.aligned.m16n8k16.row.col.f32.bf16.bf16.f32 " \
        "{%0,%1,%2,%3},{%4,%5,%6,%7},{%8,%9},{%0,%1,%2,%3};" \
        : "+f"((d)[0]), "+f"((d)[1]), "+f"((d)[2]), "+f"((d)[3]) \
        : "r"((a)[0]), "r"((a)[1]), "r"((a)[2]), "r"((a)[3]), "r"((b)[0]), "r"((b)[1]))
#define CPA16(s, g) \
    asm volatile("cp.async.cg.shared.global [%0], [%1], 16;" :: "r"(s), "l"(g))
#define CPA_COMMIT asm volatile("cp.async.commit_group;" ::: "memory")
#define CPA_WAIT(n) asm volatile("cp.async.wait_group %0;" :: "n"(n) : "memory")

__device__ __forceinline__ void split_bf16(float v, __nv_bfloat16& hi, __nv_bfloat16& lo) {
    hi = __float2bfloat16(v);
    lo = __float2bfloat16(v - __bfloat162float(hi));
}
__device__ __forceinline__ void split_pair(float a, float b,
                                           __nv_bfloat162& ph, __nv_bfloat162& pl) {
    __nv_bfloat16 h0, l0, h1, l1;
    split_bf16(a, h0, l0);
    split_bf16(b, h1, l1);
    ph.x = h0; ph.y = h1;
    pl.x = l0; pl.y = l1;
}

// ---------------- HMMA GEMM: 3-pass bf16 split -----------------------------
// mode 0: C = acc + bias ; mode 1: += res ; mode 2: reglu(acc+bias) -> Rout
#define PITCH 144
#define ABUF (128*PITCH)
#define BBUF (128*PITCH)
#define BOFF (3*ABUF)
#define GEMM_SMEM (3*(ABUF+BBUF))     /* 110592 B */
__global__ void __launch_bounds__(256, 2)
gemm_mma(const __nv_bfloat16* __restrict__ A2, const __nv_bfloat16* __restrict__ B2,
         const float* __restrict__ bias, const float* __restrict__ res,
         float* __restrict__ C, __nv_bfloat16* __restrict__ Rout,
         int Nact, int Cs, int Kpad, int mode) {
    extern __shared__ __nv_bfloat16 dsm[];
    const uint32_t sbase = smem_u32(dsm);
    const int tid = threadIdx.x, lane = tid & 31, wid = tid >> 5;
    const int wm = wid & 1, wn = wid >> 1;
    const int m0 = blockIdx.x * 128, n0 = blockIdx.y * 128;
    const int sA2 = 2 * Kpad;
    const int KC = Kpad >> 6;
    const int nsteps = 3 * KC;

    float acc[4][4][4];
#pragma unroll
    for (int a = 0; a < 4; a++)
#pragma unroll
        for (int b = 0; b < 4; b++)
#pragma unroll
            for (int c = 0; c < 4; c++) acc[a][b][c] = 0.f;

    const int rT = tid >> 3, cT = tid & 7;
    const uint32_t sA0 = sbase + rT * PITCH + cT * 16;
    const uint32_t sB0 = sbase + BOFF + rT * PITCH + cT * 16;
    const __nv_bfloat16* gA0 = A2 + (size_t)(m0 + rT) * sA2 + cT * 8;
    const __nv_bfloat16* gB0 = B2 + (size_t)(n0 + rT) * sA2 + cT * 8;

#define ISSUE(i) do { \
    int pass = ((i) >= 2 * KC) ? 2 : (((i) >= KC) ? 1 : 0); \
    int kc = (i) - pass * KC; \
    int aO = ((pass == 2) ? Kpad : 0) + kc * 64; \
    int bO = ((pass == 1) ? Kpad : 0) + kc * 64; \
    int bufi = (i) % 3; \
    uint32_t sa = sA0 + bufi * ABUF; \
    uint32_t sb = sB0 + bufi * BBUF; \
    CPA16(sa,             gA0 + aO); \
    CPA16(sa + 32*PITCH,  gA0 + aO + (size_t)32 * sA2); \
    CPA16(sa + 64*PITCH,  gA0 + aO + (size_t)64 * sA2); \
    CPA16(sa + 96*PITCH,  gA0 + aO + (size_t)96 * sA2); \
    CPA16(sb,             gB0 + bO); \
    CPA16(sb + 32*PITCH,  gB0 + bO + (size_t)32 * sA2); \
    CPA16(sb + 64*PITCH,  gB0 + bO + (size_t)64 * sA2); \
    CPA16(sb + 96*PITCH,  gB0 + bO + (size_t)96 * sA2); \
    CPA_COMMIT; \
} while (0)

    const int q = lane >> 3, rr = lane & 7;
    const uint32_t aBase = sbase +
        (uint32_t)((wm * 64 + (q & 1) * 8 + rr) * PITCH + (q >> 1) * 16);
    const uint32_t bBase = sbase + BOFF +
        (uint32_t)((wn * 32 + (q >> 1) * 8 + rr) * PITCH + (q & 1) * 16);

    ISSUE(0);
    ISSUE(1);

    for (int i = 0; i < nsteps; i++) {
        if (i == nsteps - 1) CPA_WAIT(0); else CPA_WAIT(1);
        __syncthreads();
        if (i + 2 < nsteps) ISSUE(i + 2);
        const int buf = i % 3;
        const uint32_t aB = aBase + buf * ABUF;
        const uint32_t bB = bBase + buf * BBUF;
#pragma unroll
        for (int kk = 0; kk < 4; kk++) {
            uint32_t af[4][4];
#pragma unroll
            for (int mi = 0; mi < 4; mi++)
                LDSM4(af[mi][0], af[mi][1], af[mi][2], af[mi][3],
                      aB + mi * (16 * PITCH) + kk * 32);
            uint32_t bfr[4][2];
#pragma unroll
            for (int g = 0; g < 2; g++) {
                uint32_t t0, t1, t2, t3;
                LDSM4(t0, t1, t2, t3, bB + g * (16 * PITCH) + kk * 32);
                bfr[2 * g][0] = t0;     bfr[2 * g][1] = t1;
                bfr[2 * g + 1][0] = t2; bfr[2 * g + 1][1] = t3;
            }
#pragma unroll
            for (int mi = 0; mi < 4; mi++)
#pragma unroll
                for (int ni = 0; ni < 4; ni++)
                    MMA16816(acc[mi][ni], af[mi], bfr[ni]);
        }
    }

    // epilogue
    if (mode == 2) {
#pragma unroll
        for (int mi = 0; mi < 4; mi++) {
            int r0 = m0 + wm * 64 + mi * 16 + (lane >> 2);
            __nv_bfloat16* d0 = Rout + (size_t)r0 * 1408;
            __nv_bfloat16* d1 = Rout + (size_t)(r0 + 8) * 1408;
#pragma unroll
            for (int ni = 0; ni < 4; ni++) {
                int c0 = n0 + wn * 32 + ni * 8 + (lane & 3) * 2;
                if (c0 < HID2) {
                    int j = c0 >> 1;
                    float ba = bias[j], bb = bias[NHID + j];
                    float v0 = (acc[mi][ni][0] + ba) * fmaxf(acc[mi][ni][1] + bb, 0.f);
                    float v1 = (acc[mi][ni][2] + ba) * fmaxf(acc[mi][ni][3] + bb, 0.f);
                    __nv_bfloat16 hi, lo;
                    split_bf16(v0, hi, lo); d0[j] = hi; d0[704 + j] = lo;
                    split_bf16(v1, hi, lo); d1[j] = hi; d1[704 + j] = lo;
                }
            }
        }
    } else {
#pragma unroll
        for (int mi = 0; mi < 4; mi++) {
            int r0 = m0 + wm * 64 + mi * 16 + (lane >> 2);
            float* cr0 = C + (size_t)r0 * Cs;
            float* cr1 = C + (size_t)(r0 + 8) * Cs;
            const float* rr0 = res + (size_t)r0 * Cs;
            const float* rr1 = res + (size_t)(r0 + 8) * Cs;
#pragma unroll
            for (int ni = 0; ni < 4; ni++) {
                int c0 = n0 + wn * 32 + ni * 8 + (lane & 3) * 2;
                if (c0 < Nact) {
                    float2 bv = *(const float2*)&bias[c0];
                    float2 v01 = make_float2(acc[mi][ni][0] + bv.x, acc[mi][ni][1] + bv.y);
                    float2 v23 = make_float2(acc[mi][ni][2] + bv.x, acc[mi][ni][3] + bv.y);
                    if (mode == 1) {
                        float2 ra = *(const float2*)&rr0[c0];
                        float2 rb = *(const float2*)&rr1[c0];
                        v01.x += ra.x; v01.y += ra.y;
                        v23.x += rb.x; v23.y += rb.y;
                    }
                    *(float2*)&cr0[c0] = v01;
                    *(float2*)&cr1[c0] = v23;
                }
            }
        }
    }
}

// ---------------- tensor-core fused attention ------------------------------
// Padded tokens T=144. smem layout (bytes):
//   QP  @ 0      : 16 rows x 272   (q hi|lo)          4352
//   KP  @ 4352   : 144 rows x 272  (k hi|lo)         39168
//   VT  @ 43520  : 64 rows x 592   (v^T hi|lo)       37888
//   SB  @ 81408  : 16 rows x 592   (S hi|lo)          9472
//   SF  @ 90880  : 16 rows x 160 fp32                10240
#define AQ_OFF 0
#define AK_OFF 4352
#define AV_OFF 43520
#define ASB_OFF 81408
#define ASF_OFF 90880
#define ATT_SMEM 101120
__global__ void __launch_bounds__(256, 2)
attn_mma(const float* __restrict__ qkv, __nv_bfloat16* __restrict__ a2) {
    extern __shared__ char smc[];
    const uint32_t sb = smem_u32(smc);
    float* SF = (float*)(smc + ASF_OFF);
    const int bh = blockIdx.x;
    const int b = bh >> 3, h = bh & 7;
    const float* base = qkv + (size_t)b * SEQ * QKVN + h * (3 * HDIM);
    const int t = threadIdx.x, lane = t & 31, w = t >> 5;
    const float scale = 22.62741699796952f;   // sqrt(512)

    // load k, v^T split-bf16, zero-padded tokens 129..143
    for (int idx = t; idx < 144 * 64; idx += 256) {
        int tok = idx >> 6, d = idx & 63;
        float kv = 0.f, vv = 0.f;
        if (tok < SEQ) {
            const float* row = base + (size_t)tok * QKVN;
            kv = row[HDIM + d];
            vv = row[2 * HDIM + d];
        }
        __nv_bfloat16 hi, lo;
        split_bf16(kv, hi, lo);
        *(__nv_bfloat16*)(smc + AK_OFF + tok * 272 + d * 2) = hi;
        *(__nv_bfloat16*)(smc + AK_OFF + tok * 272 + 128 + d * 2) = lo;
        split_bf16(vv, hi, lo);
        *(__nv_bfloat16*)(smc + AV_OFF + d * 592 + tok * 2) = hi;
        *(__nv_bfloat16*)(smc + AV_OFF + d * 592 + 288 + tok * 2) = lo;
    }

    const int q4 = lane >> 3, rr = lane & 7;
    const uint32_t aQ = sb + AQ_OFF +
        (uint32_t)(((q4 & 1) * 8 + rr) * 272 + (q4 >> 1) * 16);
    const uint32_t aS = sb + ASB_OFF +
        (uint32_t)(((q4 & 1) * 8 + rr) * 592 + (q4 >> 1) * 16);

    for (int blk = 0; blk < 9; blk++) {
        const int r0m = blk * 16;
        __syncthreads();   // previous block fully consumed QP/SF/SB
        // ---- load q block, pre-scaled, split ----
        {
            int r = t >> 4, d0 = (t & 15) * 4;
            int m = r0m + r;
            float4 qv = make_float4(0.f, 0.f, 0.f, 0.f);
            if (m < SEQ) qv = *(const float4*)(base + (size_t)m * QKVN + d0);
            char* qd = smc + AQ_OFF + r * 272;
            __nv_bfloat162 ph, pl;
            split_pair(qv.x * scale, qv.y * scale, ph, pl);
            *(__nv_bfloat162*)(qd + d0 * 2) = ph;
            *(__nv_bfloat162*)(qd + 128 + d0 * 2) = pl;
            split_pair(qv.z * scale, qv.w * scale, ph, pl);
            *(__nv_bfloat162*)(qd + (d0 + 2) * 2) = ph;
            *(__nv_bfloat162*)(qd + 128 + (d0 + 2) * 2) = pl;
        }
        __syncthreads();
        // ---- S = q @ k^T (mma, 3-pass) ----
        for (int g = w; g < 9; g += 8) {
            float c0[4] = {0.f, 0.f, 0.f, 0.f};
            float c1[4] = {0.f, 0.f, 0.f, 0.f};
            uint32_t bK = sb + AK_OFF +
                (uint32_t)((g * 16 + (q4 >> 1) * 8 + rr) * 272 + (q4 & 1) * 16);
#pragma unroll
            for (int p = 0; p < 3; p++) {
                int ao = (p == 2) ? 128 : 0;
                int bo = (p == 1) ? 128 : 0;
#pragma unroll
                for (int kk = 0; kk < 4; kk++) {
                    uint32_t af[4];
                    LDSM4(af[0], af[1], af[2], af[3], aQ + ao + kk * 32);
                    uint32_t t0, t1, t2, t3;
                    LDSM4(t0, t1, t2, t3, bK + bo + kk * 32);
                    uint32_t b0[2] = {t0, t1}, b1[2] = {t2, t3};
                    MMA16816(c0, af, b0);
                    MMA16816(c1, af, b1);
                }
            }
            int r = lane >> 2, cc = (lane & 3) * 2;
            int n0 = g * 16;
            SF[r * 160 + n0 + cc]           = c0[0];
            SF[r * 160 + n0 + cc + 1]       = c0[1];
            SF[(r + 8) * 160 + n0 + cc]     = c0[2];
            SF[(r + 8) * 160 + n0 + cc + 1] = c0[3];
            SF[r * 160 + n0 + 8 + cc]           = c1[0];
            SF[r * 160 + n0 + 8 + cc + 1]       = c1[1];
            SF[(r + 8) * 160 + n0 + 8 + cc]     = c1[2];
            SF[(r + 8) * 160 + n0 + 8 + cc + 1] = c1[3];
        }
        __syncthreads();
        // ---- double softmax: warp w -> rows 2w, 2w+1 ----
#pragma unroll
        for (int rs = 0; rs < 2; rs++) {
            float* p = SF + (w * 2 + rs) * 160;
            float v[5];
            int cnt = 0;
            float mx = -1e30f;
            for (int j = lane; j < SEQ; j += 32) { v[cnt] = p[j]; mx = fmaxf(mx, v[cnt]); cnt++; }
#pragma unroll
            for (int o = 16; o; o >>= 1) mx = fmaxf(mx, __shfl_xor_sync(0xffffffffu, mx, o));
            float s = 0.f;
            for (int c = 0; c < cnt; c++) { v[c] = __expf(v[c] - mx); s += v[c]; }
#pragma unroll
            for (int o = 16; o; o >>= 1) s += __shfl_xor_sync(0xffffffffu, s, o);
            float inv = 1.0f / s;
            mx = -1e30f;
            for (int c = 0; c < cnt; c++) { v[c] *= inv; mx = fmaxf(mx, v[c]); }
#pragma unroll
            for (int o = 16; o; o >>= 1) mx = fmaxf(mx, __shfl_xor_sync(0xffffffffu, mx, o));
            s = 0.f;
            for (int c = 0; c < cnt; c++) { v[c] = __expf(v[c] - mx); s += v[c]; }
#pragma unroll
            for (int o = 16; o; o >>= 1) s += __shfl_xor_sync(0xffffffffu, s, o);
            inv = 1.0f / s;
            cnt = 0;
            for (int j = lane; j < SEQ; j += 32) { p[j] = v[cnt] * inv; cnt++; }
        }
        __syncthreads();
        // ---- convert S -> split-bf16 (cols 0..143; pads are 0) ----
        for (int idx = t; idx < 16 * 72; idx += 256) {
            int r = idx / 72, c2 = (idx - r * 72) * 2;
            __nv_bfloat162 ph, pl;
            split_pair(SF[r * 160 + c2], SF[r * 160 + c2 + 1], ph, pl);
            *(__nv_bfloat162*)(smc + ASB_OFF + r * 592 + c2 * 2) = ph;
            *(__nv_bfloat162*)(smc + ASB_OFF + r * 592 + 288 + c2 * 2) = pl;
        }
        __syncthreads();
        // ---- O = S @ v (mma, 3-pass) ----
        {
            float c0[4] = {0.f, 0.f, 0.f, 0.f};
            uint32_t bV = sb + AV_OFF +
                (uint32_t)((w * 8 + (lane & 7)) * 592 + ((lane >> 3) & 1) * 16);
#pragma unroll
            for (int p = 0; p < 3; p++) {
                int ao = (p == 2) ? 288 : 0;
                int bo = (p == 1) ? 288 : 0;
#pragma unroll
                for (int kk = 0; kk < 9; kk++) {
                    uint32_t af[4];
                    LDSM4(af[0], af[1], af[2], af[3], aS + ao + kk * 32);
                    uint32_t b0[2];
                    LDSM2(b0[0], b0[1], bV + bo + kk * 32);
                    MMA16816(c0, af, b0);
                }
            }
            int r = lane >> 2, cc = (lane & 3) * 2;
            int col = h * HDIM + w * 8 + cc;
#pragma unroll
            for (int half = 0; half < 2; half++) {
                int m = r0m + r + half * 8;
                if (m < SEQ) {
                    __nv_bfloat162 ph, pl;
                    split_pair(c0[half * 2], c0[half * 2 + 1], ph, pl);
                    __nv_bfloat16* dst = a2 + ((size_t)b * SEQ + m) * 1024 + col;
                    *(__nv_bfloat162*)dst = ph;
                    *(__nv_bfloat162*)(dst + 512) = pl;
                }
            }
        }
    }
}

// ---------------- weight conversion (interleave option for W0) -------------
__global__ void convB_kernel(const float* __restrict__ W, __nv_bfloat16* __restrict__ dst,
                             int K, int N, int Kpad, size_t wStride, size_t dStride,
                             int interleave) {
    __shared__ float t[32][33];
    const float* Wl = W + blockIdx.z * wStride;
    __nv_bfloat16* dl = dst + blockIdx.z * dStride;
    int k0 = blockIdx.x * 32, n0 = blockIdx.y * 32;
    int tx = threadIdx.x, ty = threadIdx.y;
#pragma unroll
    for (int i = 0; i < 4; i++) {
        int k = k0 + ty + i * 8, n = n0 + tx;
        int nsrc = interleave ? ((n >> 1) + (n & 1) * NHID) : n;
        t[ty + i * 8][tx] = (k < K && n < N) ? Wl[(size_t)k * N + nsrc] : 0.f;
    }
    __syncthreads();
#pragma unroll
    for (int i = 0; i < 4; i++) {
        int n = n0 + ty + i * 8, k = k0 + tx;
        float v = t[tx][ty + i * 8];
        __nv_bfloat16 hi, lo; split_bf16(v, hi, lo);
        dl[(size_t)n * 2 * Kpad + k] = hi;
        dl[(size_t)n * 2 * Kpad + Kpad + k] = lo;
    }
}

// ---------------- tokenizer (vectorized; also emits split-bf16 a2) ---------
__global__ void tokenizer_kernel(const float* __restrict__ x,
                                 const float* __restrict__ tok_w,
                                 const float* __restrict__ tok_b,
                                 const float* __restrict__ cat_emb,
                                 float* __restrict__ h,
                                 __nv_bfloat16* __restrict__ a2) {
    int t = blockIdx.x;
    int b = t / SEQ, s = t % SEQ;
    int e0 = threadIdx.x * 4;      // 128 threads x 4 consecutive elems
    const float* src;
    float scale = 1.0f;
    const float* brow = nullptr;
    if (s == 0) {
        src = tok_w;
    } else if (s <= NCONT) {
        src = tok_w + (size_t)s * EMBD;
        scale = x[(size_t)b * (NCAT + NCONT) + NCAT + (s - 1)];
        brow = tok_b + (size_t)(s - 1) * EMBD;
    } else {
        int c = s - (NCONT + 1);
        int idx = (int)x[(size_t)b * (NCAT + NCONT) + c] + 100 * c;
        src = cat_emb + (size_t)idx * EMBD;
        brow = tok_b + (size_t)(s - 1) * EMBD;
    }
    float4 v = *(const float4*)&src[e0];
    v.x *= scale; v.y *= scale; v.z *= scale; v.w *= scale;
    if (brow) {
        float4 bv = *(const float4*)&brow[e0];
        v.x += bv.x; v.y += bv.y; v.z += bv.z; v.w += bv.w;
    }
    *(float4*)&h[(size_t)t * EMBD + e0] = v;
    __nv_bfloat16* da = a2 + (size_t)t * 1024;
    __nv_bfloat162 ph, pl;
    split_pair(v.x, v.y, ph, pl);
    *(__nv_bfloat162*)&da[e0] = ph;
    *(__nv_bfloat162*)&da[512 + e0] = pl;
    split_pair(v.z, v.w, ph, pl);
    *(__nv_bfloat162*)&da[e0 + 2] = ph;
    *(__nv_bfloat162*)&da[512 + e0 + 2] = pl;
}

// ---------------- layernorm -> bf16 hi/lo (vectorized) ---------------------
__global__ void ln_conv_kernel(const float* __restrict__ in,
                               const float* __restrict__ g,
                               const float* __restrict__ b,
                               __nv_bfloat16* __restrict__ out) {
    int row = blockIdx.x * 8 + threadIdx.y;
    if (row >= NTOK) return;
    const float* p = in + (size_t)row * EMBD;
    int lane = threadIdx.x;
    float2 v[8];
    float s = 0.f;
#pragma unroll
    for (int i = 0; i < 8; i++) {
        v[i] = *(const float2*)&p[lane * 2 + 64 * i];
        s += v[i].x + v[i].y;
    }
#pragma unroll
    for (int o = 16; o; o >>= 1) s += __shfl_xor_sync(0xffffffffu, s, o);
    float mean = s * (1.0f / EMBD);
    float vs = 0.f;
#pragma unroll
    for (int i = 0; i < 8; i++) {
        float dx = v[i].x - mean, dy = v[i].y - mean;
        vs += dx * dx + dy * dy;
    }
#pragma unroll
    for (int o = 16; o; o >>= 1) vs += __shfl_xor_sync(0xffffffffu, vs, o);
    float inv = rsqrtf(vs * (1.0f / EMBD) + 1e-5f);
    __nv_bfloat16* qo = out + (size_t)row * 1024;
#pragma unroll
    for (int i = 0; i < 8; i++) {
        int e = lane * 2 + 64 * i;
        float2 gg = *(const float2*)&g[e];
        float2 bb = *(const float2*)&b[e];
        float y0 = (v[i].x - mean) * inv * gg.x + bb.x;
        float y1 = (v[i].y - mean) * inv * gg.y + bb.y;
        __nv_bfloat162 ph, pl;
        split_pair(y0, y1, ph, pl);
        *(__nv_bfloat162*)&qo[e] = ph;
        *(__nv_bfloat162*)&qo[512 + e] = pl;
    }
}

// ---------------- extract CLS ----------------------------------------------
__global__ void extract_kernel(const float* __restrict__ h, float* __restrict__ out) {
    int b = blockIdx.x;
    int e = threadIdx.x * 4;
    *(float4*)&out[(size_t)b * EMBD + e] =
        *(const float4*)&h[(size_t)b * SEQ * EMBD + e];
}

// ---------------- host -----------------------------------------------------
extern "C" void kernel_launch(void* const* d_in, const int* in_sizes, int n_in,
                              void* d_out, int out_size) {
    (void)in_sizes; (void)n_in; (void)out_size;
    const float* x       = (const float*)d_in[0];
    const float* tok_w   = (const float*)d_in[1];
    const float* tok_b   = (const float*)d_in[2];
    const float* cat_emb = (const float*)d_in[3];
    const float* Wqkv    = (const float*)d_in[4];
    const float* bqkv    = (const float*)d_in[5];
    const float* Wout    = (const float*)d_in[6];
    const float* bout    = (const float*)d_in[7];
    const float* W0      = (const float*)d_in[8];
    const float* b0      = (const float*)d_in[9];
    const float* W1      = (const float*)d_in[10];
    const float* b1      = (const float*)d_in[11];
    const float* ln0_g   = (const float*)d_in[12];
    const float* ln0_b   = (const float*)d_in[13];
    const float* ln1_g   = (const float*)d_in[14];
    const float* ln1_b   = (const float*)d_in[15];
    float* out = (float*)d_out;

    float *ph, *pqkv;
    __nv_bfloat16 *pa2, *pr, *pb2;
    cudaGetSymbolAddress((void**)&ph, g_h);
    cudaGetSymbolAddress((void**)&pqkv, g_qkv);
    cudaGetSymbolAddress((void**)&pa2, g_a2);
    cudaGetSymbolAddress((void**)&pr, g_r);
    cudaGetSymbolAddress((void**)&pb2, g_b2);

    cudaFuncSetAttribute(gemm_mma, cudaFuncAttributeMaxDynamicSharedMemorySize, GEMM_SMEM);
    cudaFuncSetAttribute(attn_mma, cudaFuncAttributeMaxDynamicSharedMemorySize, ATT_SMEM);

    // zero reglu operand once (pads stay zero; data cols overwritten per layer)
    cudaMemsetAsync(pr, 0, (size_t)NTOK * 1408 * sizeof(__nv_bfloat16));

    // weight conversion, batched over all layers
    {
        __nv_bfloat16* bq  = pb2;
        __nv_bfloat16* bo  = pb2 + B2_QKV_SZ;
        __nv_bfloat16* b0p = pb2 + B2_QKV_SZ + B2_WOUT_SZ;
        __nv_bfloat16* b1p = pb2 + B2_QKV_SZ + B2_WOUT_SZ + B2_W0_SZ;
        convB_kernel<<<dim3(16, 48, NDEPTH), dim3(32, 8)>>>(
            Wqkv, bq, 512, 1536, 512, (size_t)EMBD * QKVN, B2_LAYER, 0);
        convB_kernel<<<dim3(16, 16, NDEPTH), dim3(32, 8)>>>(
            Wout, bo, 512, 512, 512, (size_t)EMBD * EMBD, B2_LAYER, 0);
        convB_kernel<<<dim3(16, 48, NDEPTH), dim3(32, 8)>>>(
            W0, b0p, 512, HID2, 512, (size_t)EMBD * HID2, B2_LAYER, 1);
        convB_kernel<<<dim3(22, 16, NDEPTH), dim3(32, 8)>>>(
            W1, b1p, NHID, 512, KPAD_H, (size_t)NHID * EMBD, B2_LAYER, 0);
    }

    tokenizer_kernel<<<NTOK, 128>>>(x, tok_w, tok_b, cat_emb, ph, pa2);

    for (int L = 0; L < NDEPTH; L++) {
        __nv_bfloat16* bq  = pb2 + (size_t)L * B2_LAYER;
        __nv_bfloat16* bo  = bq + B2_QKV_SZ;
        __nv_bfloat16* b0p = bo + B2_WOUT_SZ;
        __nv_bfloat16* b1p = b0p + B2_W0_SZ;

        if (L > 0) {
            ln_conv_kernel<<<NTOK / 8, dim3(32, 8)>>>(ph, ln0_g + L * EMBD, ln0_b + L * EMBD, pa2);
        }
        gemm_mma<<<dim3(129, 12), 256, GEMM_SMEM>>>(pa2, bq, bqkv + (size_t)L * QKVN,
                                                    nullptr, pqkv, nullptr, QKVN, QKVN, KPAD_E, 0);
        attn_mma<<<NBH, 256, ATT_SMEM>>>(pqkv, pa2);
        gemm_mma<<<dim3(129, 4), 256, GEMM_SMEM>>>(pa2, bo, bout + (size_t)L * EMBD,
                                                   ph, ph, nullptr, EMBD, EMBD, KPAD_E, 1);
        ln_conv_kernel<<<NTOK / 8, dim3(32, 8)>>>(ph, ln1_g + L * EMBD, ln1_b + L * EMBD, pa2);
        // W0 + ReGLU fused (interleaved columns) -> pr
        gemm_mma<<<dim3(129, 11), 256, GEMM_SMEM>>>(pa2, b0p, b0 + (size_t)L * HID2,
                                                    nullptr, nullptr, pr, HID2, 0, KPAD_E, 2);
        gemm_mma<<<dim3(129, 4), 256, GEMM_SMEM>>>(pr, b1p, b1 + (size_t)L * EMBD,
                                                   ph, ph, nullptr, EMBD, EMBD, KPAD_H, 1);
    }
    extract_kernel<<<BSZ, 128>>>(ph, out);
}

// round 16
// speedup vs baseline: 1.0461x; 1.0045x over previous
#include <cuda_runtime.h>
#include <cuda_bf16.h>
#include <cstdint>
#include <math.h>

#define EMBD 512
#define NHEADS 8
#define HDIM 64
#define NDEPTH 6
#define NCONT 100
#define NCAT 28
#define NHID 682
#define BSZ 128
#define SEQ 129
#define NTOK (BSZ*SEQ)      /* 16512 */
#define QKVN (3*EMBD)       /* 1536  */
#define HID2 (2*NHID)       /* 1364  */
#define NBH (BSZ*NHEADS)    /* 1024  */

#define KPAD_E 512
#define KPAD_H 704
#define W0_NPAD 1536

// ---------------- scratch (device globals) ---------------------------------
__device__ float g_h[NTOK*EMBD];
__device__ float g_qkv[NTOK*QKVN];
__device__ __nv_bfloat16 g_a2[(size_t)NTOK*1024];            // EMB-K operand
__device__ __nv_bfloat16 g_r[(size_t)NTOK*1408];             // reglu operand (Kpad=704)
#define B2_QKV_SZ ((size_t)1536*1024)
#define B2_WOUT_SZ ((size_t)512*1024)
#define B2_W0_SZ ((size_t)W0_NPAD*1024)
#define B2_W1_SZ ((size_t)512*1408)
#define B2_LAYER (B2_QKV_SZ+B2_WOUT_SZ+B2_W0_SZ+B2_W1_SZ)
__device__ __nv_bfloat16 g_b2[B2_LAYER*NDEPTH];

// ---------------- helpers ---------------------------------------------------
__device__ __forceinline__ uint32_t smem_u32(const void* p) {
    uint32_t a;
    asm("{ .reg .u64 t; cvta.to.shared.u64 t, %1; cvt.u32.u64 %0, t; }" : "=r"(a) : "l"(p));
    return a;
}
#define LDSM4(r0, r1, r2, r3, addr) \
    asm volatile("ldmatrix.sync.aligned.m8n8.x4.shared.b16 {%0,%1,%2,%3}, [%4];" \
        : "=r"(r0), "=r"(r1), "=r"(r2), "=r"(r3) : "r"(addr))
#define LDSM2(r0, r1, addr) \
    asm volatile("ldmatrix.sync.aligned.m8n8.x2.shared.b16 {%0,%1}, [%2];" \
        : "=r"(r0), "=r"(r1) : "r"(addr))
#define MMA16816(d, a, b) \
    asm volatile("mma.sync.aligned.m16n8k16.row.col.f32.bf16.bf16.f32 " \
        "{%0,%1,%2,%3},{%4,%5,%6,%7},{%8,%9},{%0,%1,%2,%3};" \
        : "+f"((d)[0]), "+f"((d)[1]), "+f"((d)[2]), "+f"((d)[3]) \
        : "r"((a)[0]), "r"((a)[1]), "r"((a)[2]), "r"((a)[3]), "r"((b)[0]), "r"((b)[1]))
#define CPA16(s, g) \
    asm volatile("cp.async.cg.shared.global [%0], [%1], 16;" :: "r"(s), "l"(g))
#define CPA_COMMIT asm volatile("cp.async.commit_group;" ::: "memory")
#define CPA_WAIT(n) asm volatile("cp.async.wait_group %0;" :: "n"(n) : "memory")

__device__ __forceinline__ void split_bf16(float v, __nv_bfloat16& hi, __nv_bfloat16& lo) {
    hi = __float2bfloat16(v);
    lo = __float2bfloat16(v - __bfloat162float(hi));
}
__device__ __forceinline__ void split_pair(float a, float b,
                                           __nv_bfloat162& ph, __nv_bfloat162& pl) {
    __nv_bfloat16 h0, l0, h1, l1;
    split_bf16(a, h0, l0);
    split_bf16(b, h1, l1);
    ph.x = h0; ph.y = h1;
    pl.x = l0; pl.y = l1;
}

// ---------------- HMMA GEMM: 3-pass bf16 split -----------------------------
// mode 0: C = acc + bias ; mode 1: += res ; mode 2: reglu(acc+bias) -> Rout
#define PITCH 144
#define ABUF (128*PITCH)
#define BBUF (128*PITCH)
#define BOFF (3*ABUF)
#define GEMM_SMEM (3*(ABUF+BBUF))     /* 110592 B */
__global__ void __launch_bounds__(256, 2)
gemm_mma(const __nv_bfloat16* __restrict__ A2, const __nv_bfloat16* __restrict__ B2,
         const float* __restrict__ bias, const float* __restrict__ res,
         float* __restrict__ C, __nv_bfloat16* __restrict__ Rout,
         int Nact, int Cs, int Kpad, int mode) {
    extern __shared__ __nv_bfloat16 dsm[];
    const uint32_t sbase = smem_u32(dsm);
    const int tid = threadIdx.x, lane = tid & 31, wid = tid >> 5;
    const int wm = wid & 1, wn = wid >> 1;
    const int m0 = blockIdx.x * 128, n0 = blockIdx.y * 128;
    const int sA2 = 2 * Kpad;
    const int KC = Kpad >> 6;
    const int nsteps = 3 * KC;

    float acc[4][4][4];
#pragma unroll
    for (int a = 0; a < 4; a++)
#pragma unroll
        for (int b = 0; b < 4; b++)
#pragma unroll
            for (int c = 0; c < 4; c++) acc[a][b][c] = 0.f;

    const int rT = tid >> 3, cT = tid & 7;
    const uint32_t sA0 = sbase + rT * PITCH + cT * 16;
    const uint32_t sB0 = sbase + BOFF + rT * PITCH + cT * 16;
    const __nv_bfloat16* gA0 = A2 + (size_t)(m0 + rT) * sA2 + cT * 8;
    const __nv_bfloat16* gB0 = B2 + (size_t)(n0 + rT) * sA2 + cT * 8;

#define ISSUE(i) do { \
    int pass = ((i) >= 2 * KC) ? 2 : (((i) >= KC) ? 1 : 0); \
    int kc = (i) - pass * KC; \
    int aO = ((pass == 2) ? Kpad : 0) + kc * 64; \
    int bO = ((pass == 1) ? Kpad : 0) + kc * 64; \
    int bufi = (i) % 3; \
    uint32_t sa = sA0 + bufi * ABUF; \
    uint32_t sb = sB0 + bufi * BBUF; \
    CPA16(sa,             gA0 + aO); \
    CPA16(sa + 32*PITCH,  gA0 + aO + (size_t)32 * sA2); \
    CPA16(sa + 64*PITCH,  gA0 + aO + (size_t)64 * sA2); \
    CPA16(sa + 96*PITCH,  gA0 + aO + (size_t)96 * sA2); \
    CPA16(sb,             gB0 + bO); \
    CPA16(sb + 32*PITCH,  gB0 + bO + (size_t)32 * sA2); \
    CPA16(sb + 64*PITCH,  gB0 + bO + (size_t)64 * sA2); \
    CPA16(sb + 96*PITCH,  gB0 + bO + (size_t)96 * sA2); \
    CPA_COMMIT; \
} while (0)

    const int q = lane >> 3, rr = lane & 7;
    const uint32_t aBase = sbase +
        (uint32_t)((wm * 64 + (q & 1) * 8 + rr) * PITCH + (q >> 1) * 16);
    const uint32_t bBase = sbase + BOFF +
        (uint32_t)((wn * 32 + (q >> 1) * 8 + rr) * PITCH + (q & 1) * 16);

    ISSUE(0);
    ISSUE(1);

    for (int i = 0; i < nsteps; i++) {
        if (i == nsteps - 1) CPA_WAIT(0); else CPA_WAIT(1);
        __syncthreads();
        if (i + 2 < nsteps) ISSUE(i + 2);
        const int buf = i % 3;
        const uint32_t aB = aBase + buf * ABUF;
        const uint32_t bB = bBase + buf * BBUF;
#pragma unroll
        for (int kk = 0; kk < 4; kk++) {
            uint32_t af[4][4];
#pragma unroll
            for (int mi = 0; mi < 4; mi++)
                LDSM4(af[mi][0], af[mi][1], af[mi][2], af[mi][3],
                      aB + mi * (16 * PITCH) + kk * 32);
            uint32_t bfr[4][2];
#pragma unroll
            for (int g = 0; g < 2; g++) {
                uint32_t t0, t1, t2, t3;
                LDSM4(t0, t1, t2, t3, bB + g * (16 * PITCH) + kk * 32);
                bfr[2 * g][0] = t0;     bfr[2 * g][1] = t1;
                bfr[2 * g + 1][0] = t2; bfr[2 * g + 1][1] = t3;
            }
#pragma unroll
            for (int mi = 0; mi < 4; mi++)
#pragma unroll
                for (int ni = 0; ni < 4; ni++)
                    MMA16816(acc[mi][ni], af[mi], bfr[ni]);
        }
    }

    // epilogue
    if (mode == 2) {
#pragma unroll
        for (int mi = 0; mi < 4; mi++) {
            int r0 = m0 + wm * 64 + mi * 16 + (lane >> 2);
            __nv_bfloat16* d0 = Rout + (size_t)r0 * 1408;
            __nv_bfloat16* d1 = Rout + (size_t)(r0 + 8) * 1408;
#pragma unroll
            for (int ni = 0; ni < 4; ni++) {
                int c0 = n0 + wn * 32 + ni * 8 + (lane & 3) * 2;
                if (c0 < HID2) {
                    int j = c0 >> 1;
                    float ba = bias[j], bb = bias[NHID + j];
                    float v0 = (acc[mi][ni][0] + ba) * fmaxf(acc[mi][ni][1] + bb, 0.f);
                    float v1 = (acc[mi][ni][2] + ba) * fmaxf(acc[mi][ni][3] + bb, 0.f);
                    __nv_bfloat16 hi, lo;
                    split_bf16(v0, hi, lo); d0[j] = hi; d0[704 + j] = lo;
                    split_bf16(v1, hi, lo); d1[j] = hi; d1[704 + j] = lo;
                }
            }
        }
    } else {
#pragma unroll
        for (int mi = 0; mi < 4; mi++) {
            int r0 = m0 + wm * 64 + mi * 16 + (lane >> 2);
            float* cr0 = C + (size_t)r0 * Cs;
            float* cr1 = C + (size_t)(r0 + 8) * Cs;
            const float* rr0 = res + (size_t)r0 * Cs;
            const float* rr1 = res + (size_t)(r0 + 8) * Cs;
#pragma unroll
            for (int ni = 0; ni < 4; ni++) {
                int c0 = n0 + wn * 32 + ni * 8 + (lane & 3) * 2;
                if (c0 < Nact) {
                    float2 bv = *(const float2*)&bias[c0];
                    float2 v01 = make_float2(acc[mi][ni][0] + bv.x, acc[mi][ni][1] + bv.y);
                    float2 v23 = make_float2(acc[mi][ni][2] + bv.x, acc[mi][ni][3] + bv.y);
                    if (mode == 1) {
                        float2 ra = *(const float2*)&rr0[c0];
                        float2 rb = *(const float2*)&rr1[c0];
                        v01.x += ra.x; v01.y += ra.y;
                        v23.x += rb.x; v23.y += rb.y;
                    }
                    *(float2*)&cr0[c0] = v01;
                    *(float2*)&cr1[c0] = v23;
                }
            }
        }
    }
}

// ---------------- tensor-core fused attention ------------------------------
// Padded tokens T=144. smem layout (bytes):
//   QP  @ 0      : 16 rows x 272   (q hi|lo)          4352
//   KP  @ 4352   : 144 rows x 272  (k hi|lo)         39168
//   VT  @ 43520  : 64 rows x 592   (v^T hi|lo)       37888
//   SB  @ 81408  : 16 rows x 592   (S hi|lo)          9472
//   SF  @ 90880  : 16 rows x 160 fp32                10240
#define AQ_OFF 0
#define AK_OFF 4352
#define AV_OFF 43520
#define ASB_OFF 81408
#define ASF_OFF 90880
#define ATT_SMEM 101120
__global__ void __launch_bounds__(256, 2)
attn_mma(const float* __restrict__ qkv, __nv_bfloat16* __restrict__ a2) {
    extern __shared__ char smc[];
    const uint32_t sb = smem_u32(smc);
    float* SF = (float*)(smc + ASF_OFF);
    const int bh = blockIdx.x;
    const int b = bh >> 3, h = bh & 7;
    const float* base = qkv + (size_t)b * SEQ * QKVN + h * (3 * HDIM);
    const int t = threadIdx.x, lane = t & 31, w = t >> 5;
    const float scale = 22.62741699796952f;   // sqrt(512)

    // load k, v^T split-bf16, zero-padded tokens 129..143
    for (int idx = t; idx < 144 * 64; idx += 256) {
        int tok = idx >> 6, d = idx & 63;
        float kv = 0.f, vv = 0.f;
        if (tok < SEQ) {
            const float* row = base + (size_t)tok * QKVN;
            kv = row[HDIM + d];
            vv = row[2 * HDIM + d];
        }
        __nv_bfloat16 hi, lo;
        split_bf16(kv, hi, lo);
        *(__nv_bfloat16*)(smc + AK_OFF + tok * 272 + d * 2) = hi;
        *(__nv_bfloat16*)(smc + AK_OFF + tok * 272 + 128 + d * 2) = lo;
        split_bf16(vv, hi, lo);
        *(__nv_bfloat16*)(smc + AV_OFF + d * 592 + tok * 2) = hi;
        *(__nv_bfloat16*)(smc + AV_OFF + d * 592 + 288 + tok * 2) = lo;
    }
    // zero SF pad cols 129..143 once (finite; multiplied by v=0 later)
    if (t < 240) {
        int r = t / 15, c = 129 + t % 15;
        SF[r * 160 + c] = 0.f;
    }

    const int q4 = lane >> 3, rr = lane & 7;
    const uint32_t aQ = sb + AQ_OFF +
        (uint32_t)(((q4 & 1) * 8 + rr) * 272 + (q4 >> 1) * 16);
    const uint32_t aS = sb + ASB_OFF +
        (uint32_t)(((q4 & 1) * 8 + rr) * 592 + (q4 >> 1) * 16);

    for (int blk = 0; blk < 9; blk++) {
        const int r0m = blk * 16;
        __syncthreads();   // previous block fully consumed QP/SF/SB
        // ---- load q block, pre-scaled, split ----
        {
            int r = t >> 4, d0 = (t & 15) * 4;
            int m = r0m + r;
            float4 qv = make_float4(0.f, 0.f, 0.f, 0.f);
            if (m < SEQ) qv = *(const float4*)(base + (size_t)m * QKVN + d0);
            char* qd = smc + AQ_OFF + r * 272;
            __nv_bfloat162 ph, pl;
            split_pair(qv.x * scale, qv.y * scale, ph, pl);
            *(__nv_bfloat162*)(qd + d0 * 2) = ph;
            *(__nv_bfloat162*)(qd + 128 + d0 * 2) = pl;
            split_pair(qv.z * scale, qv.w * scale, ph, pl);
            *(__nv_bfloat162*)(qd + (d0 + 2) * 2) = ph;
            *(__nv_bfloat162*)(qd + 128 + (d0 + 2) * 2) = pl;
        }
        __syncthreads();
        // ---- S = q @ k^T (mma, 3-pass): one 16-col key group per warp ----
        {
            const int g = w;
            float c0[4] = {0.f, 0.f, 0.f, 0.f};
            float c1[4] = {0.f, 0.f, 0.f, 0.f};
            uint32_t bK = sb + AK_OFF +
                (uint32_t)((g * 16 + (q4 >> 1) * 8 + rr) * 272 + (q4 & 1) * 16);
#pragma unroll
            for (int p = 0; p < 3; p++) {
                int ao = (p == 2) ? 128 : 0;
                int bo = (p == 1) ? 128 : 0;
#pragma unroll
                for (int kk = 0; kk < 4; kk++) {
                    uint32_t af[4];
                    LDSM4(af[0], af[1], af[2], af[3], aQ + ao + kk * 32);
                    uint32_t t0, t1, t2, t3;
                    LDSM4(t0, t1, t2, t3, bK + bo + kk * 32);
                    uint32_t b0[2] = {t0, t1}, b1[2] = {t2, t3};
                    MMA16816(c0, af, b0);
                    MMA16816(c1, af, b1);
                }
            }
            int r = lane >> 2, cc = (lane & 3) * 2;
            int n0 = g * 16;
            SF[r * 160 + n0 + cc]           = c0[0];
            SF[r * 160 + n0 + cc + 1]       = c0[1];
            SF[(r + 8) * 160 + n0 + cc]     = c0[2];
            SF[(r + 8) * 160 + n0 + cc + 1] = c0[3];
            SF[r * 160 + n0 + 8 + cc]           = c1[0];
            SF[r * 160 + n0 + 8 + cc + 1]       = c1[1];
            SF[(r + 8) * 160 + n0 + 8 + cc]     = c1[2];
            SF[(r + 8) * 160 + n0 + 8 + cc + 1] = c1[3];
        }
        // ---- warp 0: scalar S[:,128] from split operands ----
        if (w == 0) {
            int r = lane >> 1, dh = (lane & 1) * 32;
            const __nv_bfloat16* qh = (const __nv_bfloat16*)(smc + AQ_OFF + r * 272);
            const __nv_bfloat16* kh = (const __nv_bfloat16*)(smc + AK_OFF + 128 * 272);
            float acc = 0.f;
#pragma unroll
            for (int d = 0; d < 32; d++) {
                float qv = __bfloat162float(qh[dh + d]) + __bfloat162float(qh[64 + dh + d]);
                float kv = __bfloat162float(kh[dh + d]) + __bfloat162float(kh[64 + dh + d]);
                acc += qv * kv;
            }
            acc += __shfl_xor_sync(0xffffffffu, acc, 1);
            if ((lane & 1) == 0) SF[r * 160 + 128] = acc;
        }
        __syncthreads();
        // ---- double softmax: warp w -> rows 2w, 2w+1 ----
#pragma unroll
        for (int rs = 0; rs < 2; rs++) {
            float* p = SF + (w * 2 + rs) * 160;
            float v[5];
            int cnt = 0;
            float mx = -1e30f;
            for (int j = lane; j < SEQ; j += 32) { v[cnt] = p[j]; mx = fmaxf(mx, v[cnt]); cnt++; }
#pragma unroll
            for (int o = 16; o; o >>= 1) mx = fmaxf(mx, __shfl_xor_sync(0xffffffffu, mx, o));
            float s = 0.f;
            for (int c = 0; c < cnt; c++) { v[c] = __expf(v[c] - mx); s += v[c]; }
#pragma unroll
            for (int o = 16; o; o >>= 1) s += __shfl_xor_sync(0xffffffffu, s, o);
            float inv = 1.0f / s;
            // second softmax: values in [0,1] -> exp safe without max subtraction
            s = 0.f;
            for (int c = 0; c < cnt; c++) { v[c] = __expf(v[c] * inv); s += v[c]; }
#pragma unroll
            for (int o = 16; o; o >>= 1) s += __shfl_xor_sync(0xffffffffu, s, o);
            inv = 1.0f / s;
            cnt = 0;
            for (int j = lane; j < SEQ; j += 32) { p[j] = v[cnt] * inv; cnt++; }
        }
        __syncthreads();
        // ---- convert S -> split-bf16 (cols 0..143; pads finite) ----
        for (int idx = t; idx < 16 * 72; idx += 256) {
            int r = idx / 72, c2 = (idx - r * 72) * 2;
            __nv_bfloat162 ph, pl;
            split_pair(SF[r * 160 + c2], SF[r * 160 + c2 + 1], ph, pl);
            *(__nv_bfloat162*)(smc + ASB_OFF + r * 592 + c2 * 2) = ph;
            *(__nv_bfloat162*)(smc + ASB_OFF + r * 592 + 288 + c2 * 2) = pl;
        }
        __syncthreads();
        // ---- O = S @ v (mma, 3-pass) ----
        {
            float c0[4] = {0.f, 0.f, 0.f, 0.f};
            uint32_t bV = sb + AV_OFF +
                (uint32_t)((w * 8 + (lane & 7)) * 592 + ((lane >> 3) & 1) * 16);
#pragma unroll
            for (int p = 0; p < 3; p++) {
                int ao = (p == 2) ? 288 : 0;
                int bo = (p == 1) ? 288 : 0;
#pragma unroll
                for (int kk = 0; kk < 9; kk++) {
                    uint32_t af[4];
                    LDSM4(af[0], af[1], af[2], af[3], aS + ao + kk * 32);
                    uint32_t b0[2];
                    LDSM2(b0[0], b0[1], bV + bo + kk * 32);
                    MMA16816(c0, af, b0);
                }
            }
            int r = lane >> 2, cc = (lane & 3) * 2;
            int col = h * HDIM + w * 8 + cc;
#pragma unroll
            for (int half = 0; half < 2; half++) {
                int m = r0m + r + half * 8;
                if (m < SEQ) {
                    __nv_bfloat162 ph, pl;
                    split_pair(c0[half * 2], c0[half * 2 + 1], ph, pl);
                    __nv_bfloat16* dst = a2 + ((size_t)b * SEQ + m) * 1024 + col;
                    *(__nv_bfloat162*)dst = ph;
                    *(__nv_bfloat162*)(dst + 512) = pl;
                }
            }
        }
    }
}

// ---------------- weight conversion (interleave option for W0) -------------
__global__ void convB_kernel(const float* __restrict__ W, __nv_bfloat16* __restrict__ dst,
                             int K, int N, int Kpad, size_t wStride, size_t dStride,
                             int interleave) {
    __shared__ float t[32][33];
    const float* Wl = W + blockIdx.z * wStride;
    __nv_bfloat16* dl = dst + blockIdx.z * dStride;
    int k0 = blockIdx.x * 32, n0 = blockIdx.y * 32;
    int tx = threadIdx.x, ty = threadIdx.y;
#pragma unroll
    for (int i = 0; i < 4; i++) {
        int k = k0 + ty + i * 8, n = n0 + tx;
        int nsrc = interleave ? ((n >> 1) + (n & 1) * NHID) : n;
        t[ty + i * 8][tx] = (k < K && n < N) ? Wl[(size_t)k * N + nsrc] : 0.f;
    }
    __syncthreads();
#pragma unroll
    for (int i = 0; i < 4; i++) {
        int n = n0 + ty + i * 8, k = k0 + tx;
        float v = t[tx][ty + i * 8];
        __nv_bfloat16 hi, lo; split_bf16(v, hi, lo);
        dl[(size_t)n * 2 * Kpad + k] = hi;
        dl[(size_t)n * 2 * Kpad + Kpad + k] = lo;
    }
}

// ---------------- tokenizer (vectorized; also emits split-bf16 a2) ---------
__global__ void tokenizer_kernel(const float* __restrict__ x,
                                 const float* __restrict__ tok_w,
                                 const float* __restrict__ tok_b,
                                 const float* __restrict__ cat_emb,
                                 float* __restrict__ h,
                                 __nv_bfloat16* __restrict__ a2) {
    int t = blockIdx.x;
    int b = t / SEQ, s = t % SEQ;
    int e0 = threadIdx.x * 4;
    const float* src;
    float scale = 1.0f;
    const float* brow = nullptr;
    if (s == 0) {
        src = tok_w;
    } else if (s <= NCONT) {
        src = tok_w + (size_t)s * EMBD;
        scale = x[(size_t)b * (NCAT + NCONT) + NCAT + (s - 1)];
        brow = tok_b + (size_t)(s - 1) * EMBD;
    } else {
        int c = s - (NCONT + 1);
        int idx = (int)x[(size_t)b * (NCAT + NCONT) + c] + 100 * c;
        src = cat_emb + (size_t)idx * EMBD;
        brow = tok_b + (size_t)(s - 1) * EMBD;
    }
    float4 v = *(const float4*)&src[e0];
    v.x *= scale; v.y *= scale; v.z *= scale; v.w *= scale;
    if (brow) {
        float4 bv = *(const float4*)&brow[e0];
        v.x += bv.x; v.y += bv.y; v.z += bv.z; v.w += bv.w;
    }
    *(float4*)&h[(size_t)t * EMBD + e0] = v;
    __nv_bfloat16* da = a2 + (size_t)t * 1024;
    __nv_bfloat162 ph, pl;
    split_pair(v.x, v.y, ph, pl);
    *(__nv_bfloat162*)&da[e0] = ph;
    *(__nv_bfloat162*)&da[512 + e0] = pl;
    split_pair(v.z, v.w, ph, pl);
    *(__nv_bfloat162*)&da[e0 + 2] = ph;
    *(__nv_bfloat162*)&da[512 + e0 + 2] = pl;
}

// ---------------- layernorm -> bf16 hi/lo (vectorized) ---------------------
__global__ void ln_conv_kernel(const float* __restrict__ in,
                               const float* __restrict__ g,
                               const float* __restrict__ b,
                               __nv_bfloat16* __restrict__ out) {
    int row = blockIdx.x * 8 + threadIdx.y;
    if (row >= NTOK) return;
    const float* p = in + (size_t)row * EMBD;
    int lane = threadIdx.x;
    float2 v[8];
    float s = 0.f;
#pragma unroll
    for (int i = 0; i < 8; i++) {
        v[i] = *(const float2*)&p[lane * 2 + 64 * i];
        s += v[i].x + v[i].y;
    }
#pragma unroll
    for (int o = 16; o; o >>= 1) s += __shfl_xor_sync(0xffffffffu, s, o);
    float mean = s * (1.0f / EMBD);
    float vs = 0.f;
#pragma unroll
    for (int i = 0; i < 8; i++) {
        float dx = v[i].x - mean, dy = v[i].y - mean;
        vs += dx * dx + dy * dy;
    }
#pragma unroll
    for (int o = 16; o; o >>= 1) vs += __shfl_xor_sync(0xffffffffu, vs, o);
    float inv = rsqrtf(vs * (1.0f / EMBD) + 1e-5f);
    __nv_bfloat16* qo = out + (size_t)row * 1024;
#pragma unroll
    for (int i = 0; i < 8; i++) {
        int e = lane * 2 + 64 * i;
        float2 gg = *(const float2*)&g[e];
        float2 bb = *(const float2*)&b[e];
        float y0 = (v[i].x - mean) * inv * gg.x + bb.x;
        float y1 = (v[i].y - mean) * inv * gg.y + bb.y;
        __nv_bfloat162 ph, pl;
        split_pair(y0, y1, ph, pl);
        *(__nv_bfloat162*)&qo[e] = ph;
        *(__nv_bfloat162*)&qo[512 + e] = pl;
    }
}

// ---------------- extract CLS ----------------------------------------------
__global__ void extract_kernel(const float* __restrict__ h, float* __restrict__ out) {
    int b = blockIdx.x;
    int e = threadIdx.x * 4;
    *(float4*)&out[(size_t)b * EMBD + e] =
        *(const float4*)&h[(size_t)b * SEQ * EMBD + e];
}

// ---------------- host -----------------------------------------------------
extern "C" void kernel_launch(void* const* d_in, const int* in_sizes, int n_in,
                              void* d_out, int out_size) {
    (void)in_sizes; (void)n_in; (void)out_size;
    const float* x       = (const float*)d_in[0];
    const float* tok_w   = (const float*)d_in[1];
    const float* tok_b   = (const float*)d_in[2];
    const float* cat_emb = (const float*)d_in[3];
    const float* Wqkv    = (const float*)d_in[4];
    const float* bqkv    = (const float*)d_in[5];
    const float* Wout    = (const float*)d_in[6];
    const float* bout    = (const float*)d_in[7];
    const float* W0      = (const float*)d_in[8];
    const float* b0      = (const float*)d_in[9];
    const float* W1      = (const float*)d_in[10];
    const float* b1      = (const float*)d_in[11];
    const float* ln0_g   = (const float*)d_in[12];
    const float* ln0_b   = (const float*)d_in[13];
    const float* ln1_g   = (const float*)d_in[14];
    const float* ln1_b   = (const float*)d_in[15];
    float* out = (float*)d_out;

    float *ph, *pqkv;
    __nv_bfloat16 *pa2, *pr, *pb2;
    cudaGetSymbolAddress((void**)&ph, g_h);
    cudaGetSymbolAddress((void**)&pqkv, g_qkv);
    cudaGetSymbolAddress((void**)&pa2, g_a2);
    cudaGetSymbolAddress((void**)&pr, g_r);
    cudaGetSymbolAddress((void**)&pb2, g_b2);

    cudaFuncSetAttribute(gemm_mma, cudaFuncAttributeMaxDynamicSharedMemorySize, GEMM_SMEM);
    cudaFuncSetAttribute(attn_mma, cudaFuncAttributeMaxDynamicSharedMemorySize, ATT_SMEM);

    // zero reglu operand once (pads stay zero; data cols overwritten per layer)
    cudaMemsetAsync(pr, 0, (size_t)NTOK * 1408 * sizeof(__nv_bfloat16));

    // weight conversion, batched over all layers
    {
        __nv_bfloat16* bq  = pb2;
        __nv_bfloat16* bo  = pb2 + B2_QKV_SZ;
        __nv_bfloat16* b0p = pb2 + B2_QKV_SZ + B2_WOUT_SZ;
        __nv_bfloat16* b1p = pb2 + B2_QKV_SZ + B2_WOUT_SZ + B2_W0_SZ;
        convB_kernel<<<dim3(16, 48, NDEPTH), dim3(32, 8)>>>(
            Wqkv, bq, 512, 1536, 512, (size_t)EMBD * QKVN, B2_LAYER, 0);
        convB_kernel<<<dim3(16, 16, NDEPTH), dim3(32, 8)>>>(
            Wout, bo, 512, 512, 512, (size_t)EMBD * EMBD, B2_LAYER, 0);
        convB_kernel<<<dim3(16, 48, NDEPTH), dim3(32, 8)>>>(
            W0, b0p, 512, HID2, 512, (size_t)EMBD * HID2, B2_LAYER, 1);
        convB_kernel<<<dim3(22, 16, NDEPTH), dim3(32, 8)>>>(
            W1, b1p, NHID, 512, KPAD_H, (size_t)NHID * EMBD, B2_LAYER, 0);
    }

    tokenizer_kernel<<<NTOK, 128>>>(x, tok_w, tok_b, cat_emb, ph, pa2);

    for (int L = 0; L < NDEPTH; L++) {
        __nv_bfloat16* bq  = pb2 + (size_t)L * B2_LAYER;
        __nv_bfloat16* bo  = bq + B2_QKV_SZ;
        __nv_bfloat16* b0p = bo + B2_WOUT_SZ;
        __nv_bfloat16* b1p = b0p + B2_W0_SZ;

        if (L > 0) {
            ln_conv_kernel<<<NTOK / 8, dim3(32, 8)>>>(ph, ln0_g + L * EMBD, ln0_b + L * EMBD, pa2);
        }
        gemm_mma<<<dim3(129, 12), 256, GEMM_SMEM>>>(pa2, bq, bqkv + (size_t)L * QKVN,
                                                    nullptr, pqkv, nullptr, QKVN, QKVN, KPAD_E, 0);
        attn_mma<<<NBH, 256, ATT_SMEM>>>(pqkv, pa2);
        gemm_mma<<<dim3(129, 4), 256, GEMM_SMEM>>>(pa2, bo, bout + (size_t)L * EMBD,
                                                   ph, ph, nullptr, EMBD, EMBD, KPAD_E, 1);
        ln_conv_kernel<<<NTOK / 8, dim3(32, 8)>>>(ph, ln1_g + L * EMBD, ln1_b + L * EMBD, pa2);
        // W0 + ReGLU fused (interleaved columns) -> pr
        gemm_mma<<<dim3(129, 11), 256, GEMM_SMEM>>>(pa2, b0p, b0 + (size_t)L * HID2,
                                                    nullptr, nullptr, pr, HID2, 0, KPAD_E, 2);
        gemm_mma<<<dim3(129, 4), 256, GEMM_SMEM>>>(pr, b1p, b1 + (size_t)L * EMBD,
                                                   ph, ph, nullptr, EMBD, EMBD, KPAD_H, 1);
    }
    extract_kernel<<<BSZ, 128>>>(ph, out);
}